// round 4
// baseline (speedup 1.0000x reference)
#include <cuda_runtime.h>
#include <cuda_bf16.h>
#include <math.h>
#include <stdint.h>

// ---------------- problem constants ----------------
#define MM   32      // state dim m
#define NN   16      // obs dim n
#define BB   256     // batch
#define TT   8       // time steps
#define HQ   1024    // m*m
#define HS   256     // n*n
#define D_Q_IN   160      // m*IN_MULT
#define D_SIG_IN 1184     // HQ + 160
#define D_S_IN   416      // 256 + 160
#define D_FC2_IN 1280     // HQ + HS
#define D_FC2_H  2560

// ---------------- device scratch (no allocations allowed) ----------------
__device__ float g_hQ  [2][BB * HQ];
__device__ float g_cQ  [BB * HQ];
__device__ float g_hSig[2][BB * HQ];
__device__ float g_cSig[BB * HQ];
__device__ float g_hS  [2][BB * HS];
__device__ float g_cS  [BB * HS];
__device__ float g_out5[BB * D_Q_IN];
__device__ float g_out6[BB * D_Q_IN];
__device__ float g_out7[BB * D_Q_IN];
__device__ float g_out1[BB * HS];
__device__ float g_a2  [BB * D_FC2_H];
__device__ float g_kvec[BB * NN * MM];
__device__ float g_xprior[2][BB * MM];
__device__ float g_dy   [BB * NN];
__device__ float g_yprev0[BB * NN];
// packed (gate-interleaved) LSTM weights + combined biases
__device__ float g_WqihP [4 * HQ * D_Q_IN];
__device__ float g_WqhhP [4 * HQ * HQ];
__device__ float g_WsigihP[4 * HQ * D_SIG_IN];
__device__ float g_WsighhP[4 * HQ * HQ];
__device__ float g_WsihP [4 * HS * D_S_IN];
__device__ float g_WshhP [4 * HS * HS];
__device__ float g_bqP  [4 * HQ];
__device__ float g_bsigP[4 * HQ];
__device__ float g_bsP  [4 * HS];

__device__ __forceinline__ float sigmoidf(float x) { return 1.f / (1.f + expf(-x)); }

// ---------------- weight pack: row rp=j*4+g <- row g*H+j; bias sum ----------------
__global__ void pack_lstm(const float* __restrict__ Wih, const float* __restrict__ Whh,
                          const float* __restrict__ bih, const float* __restrict__ bhh,
                          float* __restrict__ Wihp, float* __restrict__ Whhp,
                          float* __restrict__ bp, int H, int Kih, int Khh)
{
    int rp = blockIdx.x;           // 0 .. 4H-1
    int g = rp & 3, j = rp >> 2;
    int ro = g * H + j;
    const float4* s1 = (const float4*)(Wih + (size_t)ro * Kih);
    float4*       d1 = (float4*)(Wihp + (size_t)rp * Kih);
    for (int k = threadIdx.x; k < (Kih >> 2); k += blockDim.x) d1[k] = s1[k];
    const float4* s2 = (const float4*)(Whh + (size_t)ro * Khh);
    float4*       d2 = (float4*)(Whhp + (size_t)rp * Khh);
    for (int k = threadIdx.x; k < (Khh >> 2); k += blockDim.x) d2[k] = s2[k];
    if (threadIdx.x == 0) bp[rp] = bih[ro] + bhh[ro];
}

// ---------------- init: zero states, y_prev0 = tanh(x0[:, :16]) ----------------
__global__ void init_kernel(const float* __restrict__ x0, float* __restrict__ yprev0)
{
    int idx = blockIdx.x * blockDim.x + threadIdx.x;
    if (idx < BB * HQ) {
        g_hQ[0][idx] = 0.f; g_hQ[1][idx] = 0.f; g_cQ[idx] = 0.f;
        g_hSig[0][idx] = 0.f; g_hSig[1][idx] = 0.f; g_cSig[idx] = 0.f;
    }
    if (idx < BB * HS) { g_hS[0][idx] = 0.f; g_hS[1][idx] = 0.f; g_cS[idx] = 0.f; }
    if (idx < BB * NN) {
        int b = idx / NN, n = idx % NN;
        yprev0[idx] = tanhf(x0[b * MM + n]);
    }
}

// ---------------- fused prologue + fc5/6/7 ----------------
// grid = BB, block = 192 (warp 0 does features; all threads do the 3 small FCs)
__global__ void pre_fc_kernel(const float* __restrict__ x_post,
                              const float* __restrict__ x_post_prev,
                              const float* __restrict__ x_prior_prev,
                              const float* __restrict__ y_t,
                              const float* __restrict__ y_prev,
                              float* __restrict__ x_prior,
                              float* __restrict__ dy_buf,
                              const float* __restrict__ w5, const float* __restrict__ b5,
                              const float* __restrict__ w6, const float* __restrict__ b6,
                              const float* __restrict__ w7, const float* __restrict__ b7,
                              float* __restrict__ out5,
                              float* __restrict__ out6,
                              float* __restrict__ out7)
{
    int b = blockIdx.x;
    int tid = threadIdx.x;
    __shared__ float fwu[32], fwe[32], obs[32];

    if (tid < 32) {
        int lane = tid;
        float xp   = x_post[b * MM + lane];
        float xpp  = x_post_prev[b * MM + lane];
        float xprp = x_prior_prev[b * MM + lane];

        float xpr = xp + 0.1f * sinf(xp);
        x_prior[b * MM + lane] = xpr;

        float de = xp - xpp;
        float du = xp - xprp;
        float se = de * de, su = du * du;
        #pragma unroll
        for (int o = 16; o > 0; o >>= 1) {
            se += __shfl_xor_sync(0xffffffffu, se, o);
            su += __shfl_xor_sync(0xffffffffu, su, o);
        }
        fwe[lane] = de / fmaxf(sqrtf(se), 1e-12f);
        fwu[lane] = du / fmaxf(sqrtf(su), 1e-12f);

        float y     = (lane < NN) ? y_t[b * NN + lane]    : 0.f;
        float ypv   = (lane < NN) ? y_prev[b * NN + lane] : 0.f;
        float ypred = (lane < NN) ? tanhf(xpr)            : 0.f;
        float d1 = y - ypv;
        float d2 = y - ypred;
        if (lane < NN) dy_buf[b * NN + lane] = d2;
        float s1 = d1 * d1, s2 = d2 * d2;
        #pragma unroll
        for (int o = 16; o > 0; o >>= 1) {
            s1 += __shfl_xor_sync(0xffffffffu, s1, o);
            s2 += __shfl_xor_sync(0xffffffffu, s2, o);
        }
        if (lane < NN) {
            obs[lane]      = d1 / fmaxf(sqrtf(s1), 1e-12f);
            obs[NN + lane] = d2 / fmaxf(sqrtf(s2), 1e-12f);
        }
    }
    __syncthreads();

    for (int o = tid; o < 480; o += 192) {
        int which = o / 160, oo = o - which * 160;
        const float* W; const float* Bv; const float* xs; float* O;
        if (which == 0)      { W = w5; Bv = b5; xs = fwu; O = out5; }
        else if (which == 1) { W = w6; Bv = b6; xs = fwe; O = out6; }
        else                 { W = w7; Bv = b7; xs = obs; O = out7; }
        float acc = Bv[oo];
        const float* wr = W + oo * 32;
        #pragma unroll
        for (int k = 0; k < 32; k++) acc += xs[k] * wr[k];
        O[b * 160 + oo] = fmaxf(acc, 0.f);
    }
}

// ---------------- TF32 tensor-core multi-segment GEMM, 3-stage cp.async ----------------
// mode 0: Z[b,o] = act( sum + bias0 (+bias1) )
// mode 1: packed-LSTM epilogue: cols are gate-interleaved (j*4+g); computes c,h in place.
struct GSeg {
    const float* X;   // [BB, K] contiguous
    const float* W;   // row-major, row stride ldw
    int K;
    int ldw;
};

#define LDA 20   // padded smem stride

__device__ __forceinline__ void cpa16(void* s, const void* g) {
    uint32_t sa = (uint32_t)__cvta_generic_to_shared(s);
    asm volatile("cp.async.cg.shared.global [%0], [%1], 16;\n" :: "r"(sa), "l"(g));
}
__device__ __forceinline__ uint32_t f2tf32(float f) {
    uint32_t u;
    asm("cvt.rna.tf32.f32 %0, %1;" : "=r"(u) : "f"(f));
    return u;
}

__global__ void __launch_bounds__(256) gemm_tc(
    GSeg s0, GSeg s1, GSeg s2, int nseg,
    const float* __restrict__ bias0, const float* __restrict__ bias1,
    float* __restrict__ Z, int Nout, int act,
    int mode, float* __restrict__ cst, float* __restrict__ hout, int H)
{
    __shared__ float As[3][128 * LDA];
    __shared__ float Bs[3][64 * LDA];

    int tid  = threadIdx.x;
    int lane = tid & 31;
    int wid  = tid >> 5;
    int wm   = wid & 3;
    int wn   = wid >> 2;
    int gid  = lane >> 2;
    int tg   = lane & 3;

    int row0 = blockIdx.y * 128;
    int col0 = blockIdx.x * 64;

    int arow = tid >> 2;
    int acol = (tid & 3) * 4;

    int totK = s0.K + ((nseg > 1) ? s1.K : 0) + ((nseg > 2) ? s2.K : 0);
    int niter = totK >> 4;

    float c[2][4][4];
    #pragma unroll
    for (int mt = 0; mt < 2; mt++)
        #pragma unroll
        for (int nt = 0; nt < 4; nt++)
            #pragma unroll
            for (int r = 0; r < 4; r++) c[mt][nt][r] = 0.f;

    auto issue = [&](int it, int p) {
        int kb = it << 4;
        const float* X = s0.X; const float* W = s0.W; int K = s0.K; int ldw = s0.ldw;
        if (kb >= s0.K) {
            kb -= s0.K;
            if (nseg > 2 && kb >= s1.K) { kb -= s1.K; X = s2.X; W = s2.W; K = s2.K; ldw = s2.ldw; }
            else                        {             X = s1.X; W = s1.W; K = s1.K; ldw = s1.ldw; }
        }
        const float* xsrc = X + (size_t)(row0 + arow) * K + kb + acol;
        cpa16(&As[p][arow * LDA + acol],        xsrc);
        cpa16(&As[p][(arow + 64) * LDA + acol], xsrc + (size_t)64 * K);
        cpa16(&Bs[p][arow * LDA + acol],
              W + (size_t)(col0 + arow) * ldw + kb + acol);
        asm volatile("cp.async.commit_group;\n" ::);
    };

    issue(0, 0);
    if (niter > 1) issue(1, 1);

    for (int it = 0; it < niter; it++) {
        int p = it % 3;
        if (it < niter - 1) {
            asm volatile("cp.async.wait_group 1;\n" ::);
        } else {
            asm volatile("cp.async.wait_group 0;\n" ::);
        }
        __syncthreads();
        if (it + 2 < niter) issue(it + 2, (it + 2) % 3);

        #pragma unroll
        for (int ks = 0; ks < 2; ks++) {
            int kk = ks * 8;
            uint32_t af[2][4];
            #pragma unroll
            for (int mt = 0; mt < 2; mt++) {
                int r = wm * 32 + mt * 16 + gid;
                af[mt][0] = f2tf32(As[p][r * LDA + kk + tg]);
                af[mt][1] = f2tf32(As[p][(r + 8) * LDA + kk + tg]);
                af[mt][2] = f2tf32(As[p][r * LDA + kk + tg + 4]);
                af[mt][3] = f2tf32(As[p][(r + 8) * LDA + kk + tg + 4]);
            }
            uint32_t bf[4][2];
            #pragma unroll
            for (int nt = 0; nt < 4; nt++) {
                int n = wn * 32 + nt * 8 + gid;
                bf[nt][0] = f2tf32(Bs[p][n * LDA + kk + tg]);
                bf[nt][1] = f2tf32(Bs[p][n * LDA + kk + tg + 4]);
            }
            #pragma unroll
            for (int mt = 0; mt < 2; mt++)
                #pragma unroll
                for (int nt = 0; nt < 4; nt++) {
                    asm volatile(
                        "mma.sync.aligned.m16n8k8.row.col.f32.tf32.tf32.f32 "
                        "{%0,%1,%2,%3}, {%4,%5,%6,%7}, {%8,%9}, {%0,%1,%2,%3};\n"
                        : "+f"(c[mt][nt][0]), "+f"(c[mt][nt][1]),
                          "+f"(c[mt][nt][2]), "+f"(c[mt][nt][3])
                        : "r"(af[mt][0]), "r"(af[mt][1]), "r"(af[mt][2]), "r"(af[mt][3]),
                          "r"(bf[nt][0]), "r"(bf[nt][1]));
                }
        }
        __syncthreads();
    }

    if (mode == 0) {
        #pragma unroll
        for (int mt = 0; mt < 2; mt++) {
            int r = row0 + wm * 32 + mt * 16 + gid;
            #pragma unroll
            for (int nt = 0; nt < 4; nt++) {
                int cb = col0 + wn * 32 + nt * 8 + tg * 2;
                float b0a = bias0[cb], b0b = bias0[cb + 1];
                if (bias1) { b0a += bias1[cb]; b0b += bias1[cb + 1]; }
                float v0 = c[mt][nt][0] + b0a;
                float v1 = c[mt][nt][1] + b0b;
                float v2 = c[mt][nt][2] + b0a;
                float v3 = c[mt][nt][3] + b0b;
                if (act) {
                    v0 = fmaxf(v0, 0.f); v1 = fmaxf(v1, 0.f);
                    v2 = fmaxf(v2, 0.f); v3 = fmaxf(v3, 0.f);
                }
                *reinterpret_cast<float2*>(&Z[(size_t)r * Nout + cb])       = make_float2(v0, v1);
                *reinterpret_cast<float2*>(&Z[(size_t)(r + 8) * Nout + cb]) = make_float2(v2, v3);
            }
        }
    } else {
        // fused LSTM cell: even-tg lane holds (i,f), partner lane^1 holds (g,o)
        #pragma unroll
        for (int mt = 0; mt < 2; mt++) {
            int r = row0 + wm * 32 + mt * 16 + gid;
            #pragma unroll
            for (int nt = 0; nt < 4; nt++) {
                int cb = col0 + wn * 32 + nt * 8 + tg * 2;
                float b0a = bias0[cb], b0b = bias0[cb + 1];
                float z0 = c[mt][nt][0] + b0a;
                float z1 = c[mt][nt][1] + b0b;
                float z2 = c[mt][nt][2] + b0a;
                float z3 = c[mt][nt][3] + b0b;
                float p0 = __shfl_xor_sync(0xffffffffu, z0, 1);
                float p1 = __shfl_xor_sync(0xffffffffu, z1, 1);
                float p2 = __shfl_xor_sync(0xffffffffu, z2, 1);
                float p3 = __shfl_xor_sync(0xffffffffu, z3, 1);
                if ((tg & 1) == 0) {
                    int jj = cb >> 2;
                    {
                        float si = sigmoidf(z0), sf = sigmoidf(z1);
                        float gg = tanhf(p0),    so = sigmoidf(p1);
                        float cn = sf * cst[(size_t)r * H + jj] + si * gg;
                        cst[(size_t)r * H + jj] = cn;
                        hout[(size_t)r * H + jj] = so * tanhf(cn);
                    }
                    {
                        float si = sigmoidf(z2), sf = sigmoidf(z3);
                        float gg = tanhf(p2),    so = sigmoidf(p3);
                        float cn = sf * cst[(size_t)(r + 8) * H + jj] + si * gg;
                        cst[(size_t)(r + 8) * H + jj] = cn;
                        hout[(size_t)(r + 8) * H + jj] = so * tanhf(cn);
                    }
                }
            }
        }
    }
}

// ---------------- KF update: x_post = x_prior + K @ dy ----------------
__global__ void update_kernel(const float* __restrict__ x_prior,
                              const float* __restrict__ kvec,
                              const float* __restrict__ dy,
                              float* __restrict__ out)
{
    int b = blockIdx.x;
    int m = threadIdx.x;
    __shared__ float dys[NN];
    if (m < NN) dys[m] = dy[b * NN + m];
    __syncthreads();
    float acc = x_prior[b * MM + m];
    const float* Kr = kvec + (size_t)b * MM * NN + m * NN;
    #pragma unroll
    for (int n = 0; n < NN; n++) acc += Kr[n] * dys[n];
    out[b * MM + m] = acc;
}

// ---------------- host orchestration ----------------
extern "C" void kernel_launch(void* const* d_in, const int* in_sizes, int n_in,
                              void* d_out, int out_size)
{
    const float* Y       = (const float*)d_in[0];
    const float* x0      = (const float*)d_in[1];
    const float* Wq_ih   = (const float*)d_in[2];
    const float* Wq_hh   = (const float*)d_in[3];
    const float* bq_ih   = (const float*)d_in[4];
    const float* bq_hh   = (const float*)d_in[5];
    const float* Wsig_ih = (const float*)d_in[6];
    const float* Wsig_hh = (const float*)d_in[7];
    const float* bsig_ih = (const float*)d_in[8];
    const float* bsig_hh = (const float*)d_in[9];
    const float* Ws_ih   = (const float*)d_in[10];
    const float* Ws_hh   = (const float*)d_in[11];
    const float* bs_ih   = (const float*)d_in[12];
    const float* bs_hh   = (const float*)d_in[13];
    const float* fc1_w   = (const float*)d_in[14];
    const float* fc1_b   = (const float*)d_in[15];
    const float* fc2a_w  = (const float*)d_in[16];
    const float* fc2a_b  = (const float*)d_in[17];
    const float* fc2b_w  = (const float*)d_in[18];
    const float* fc2b_b  = (const float*)d_in[19];
    const float* fc5_w   = (const float*)d_in[20];
    const float* fc5_b   = (const float*)d_in[21];
    const float* fc6_w   = (const float*)d_in[22];
    const float* fc6_b   = (const float*)d_in[23];
    const float* fc7_w   = (const float*)d_in[24];
    const float* fc7_b   = (const float*)d_in[25];

    float* out = (float*)d_out;   // [T, B, M, 1]

    float *hQ0, *cQ, *hSig0, *cSig, *hS0, *cS;
    float *out5, *out6, *out7, *out1, *a2, *kvec;
    float *xprior0, *dy, *yprev0;
    float *WqihP, *WqhhP, *WsigihP, *WsighhP, *WsihP, *WshhP, *bqP, *bsigP, *bsP;
    cudaGetSymbolAddress((void**)&hQ0,   g_hQ);
    cudaGetSymbolAddress((void**)&cQ,    g_cQ);
    cudaGetSymbolAddress((void**)&hSig0, g_hSig);
    cudaGetSymbolAddress((void**)&cSig,  g_cSig);
    cudaGetSymbolAddress((void**)&hS0,   g_hS);
    cudaGetSymbolAddress((void**)&cS,    g_cS);
    cudaGetSymbolAddress((void**)&out5,  g_out5);
    cudaGetSymbolAddress((void**)&out6,  g_out6);
    cudaGetSymbolAddress((void**)&out7,  g_out7);
    cudaGetSymbolAddress((void**)&out1,  g_out1);
    cudaGetSymbolAddress((void**)&a2,    g_a2);
    cudaGetSymbolAddress((void**)&kvec,  g_kvec);
    cudaGetSymbolAddress((void**)&xprior0, g_xprior);
    cudaGetSymbolAddress((void**)&dy,    g_dy);
    cudaGetSymbolAddress((void**)&yprev0,g_yprev0);
    cudaGetSymbolAddress((void**)&WqihP,   g_WqihP);
    cudaGetSymbolAddress((void**)&WqhhP,   g_WqhhP);
    cudaGetSymbolAddress((void**)&WsigihP, g_WsigihP);
    cudaGetSymbolAddress((void**)&WsighhP, g_WsighhP);
    cudaGetSymbolAddress((void**)&WsihP,   g_WsihP);
    cudaGetSymbolAddress((void**)&WshhP,   g_WshhP);
    cudaGetSymbolAddress((void**)&bqP,     g_bqP);
    cudaGetSymbolAddress((void**)&bsigP,   g_bsigP);
    cudaGetSymbolAddress((void**)&bsP,     g_bsP);

    float* hQ[2]   = {hQ0,   hQ0   + BB * HQ};
    float* hSig[2] = {hSig0, hSig0 + BB * HQ};
    float* hS[2]   = {hS0,   hS0   + BB * HS};
    float* xprior_buf[2] = {xprior0, xprior0 + BB * MM};

    const GSeg nil = {nullptr, nullptr, 0, 0};

    // one-time per replay: pack LSTM weights gate-interleaved
    pack_lstm<<<4 * HQ, 128>>>(Wq_ih, Wq_hh, bq_ih, bq_hh, WqihP, WqhhP, bqP,
                               HQ, D_Q_IN, HQ);
    pack_lstm<<<4 * HQ, 128>>>(Wsig_ih, Wsig_hh, bsig_ih, bsig_hh, WsigihP, WsighhP, bsigP,
                               HQ, D_SIG_IN, HQ);
    pack_lstm<<<4 * HS, 128>>>(Ws_ih, Ws_hh, bs_ih, bs_hh, WsihP, WshhP, bsP,
                               HS, D_S_IN, HS);

    init_kernel<<<(BB * HQ + 255) / 256, 256>>>(x0, yprev0);

    for (int t = 0; t < TT; t++) {
        const float* x_post      = (t == 0) ? x0 : out + (size_t)(t - 1) * BB * MM;
        const float* x_post_prev = (t <= 1) ? x0 : out + (size_t)(t - 2) * BB * MM;
        const float* x_prior_prev= (t == 0) ? x0 : xprior_buf[(t - 1) & 1];
        const float* y_t         = Y + (size_t)t * BB * NN;
        const float* y_prev      = (t == 0) ? yprev0 : Y + (size_t)(t - 1) * BB * NN;
        float* x_prior           = xprior_buf[t & 1];
        int rd = t & 1, wr = rd ^ 1;

        pre_fc_kernel<<<BB, 192>>>(x_post, x_post_prev, x_prior_prev, y_t, y_prev,
                                   x_prior, dy,
                                   fc5_w, fc5_b, fc6_w, fc6_b, fc7_w, fc7_b,
                                   out5, out6, out7);

        // LSTM Q (fused cell epilogue)
        {
            GSeg a = {out5,   WqihP, D_Q_IN, D_Q_IN};
            GSeg b = {hQ[rd], WqhhP, HQ,     HQ};
            gemm_tc<<<dim3(4 * HQ / 64, BB / 128), 256>>>(a, b, nil, 2, bqP, nullptr,
                nullptr, 0, 0, 1, cQ, hQ[wr], HQ);
        }

        // LSTM Sigma: input = concat(hQ_new, out6)
        {
            GSeg a = {hQ[wr],   WsigihP,        HQ,     D_SIG_IN};
            GSeg b = {out6,     WsigihP + HQ,   D_Q_IN, D_SIG_IN};
            GSeg c = {hSig[rd], WsighhP,        HQ,     HQ};
            gemm_tc<<<dim3(4 * HQ / 64, BB / 128), 256>>>(a, b, c, 3, bsigP, nullptr,
                nullptr, 0, 0, 1, cSig, hSig[wr], HQ);
        }

        // fc1: relu(hSig_new @ fc1_w^T + b)
        {
            GSeg a = {hSig[wr], fc1_w, HQ, HQ};
            gemm_tc<<<dim3(HS / 64, BB / 128), 256>>>(a, nil, nil, 1, fc1_b, nullptr,
                out1, HS, 1, 0, nullptr, nullptr, 0);
        }

        // LSTM S: input = concat(out1, out7) (fused cell epilogue)
        {
            GSeg a = {out1,   WsihP,       HS,     D_S_IN};
            GSeg b = {out7,   WsihP + HS,  D_Q_IN, D_S_IN};
            GSeg c = {hS[rd], WshhP,       HS,     HS};
            gemm_tc<<<dim3(4 * HS / 64, BB / 128), 256>>>(a, b, c, 3, bsP, nullptr,
                nullptr, 0, 0, 1, cS, hS[wr], HS);
        }

        // fc2a: relu(concat(hSig_new, hS_new) @ fc2a_w^T + b)
        {
            GSeg a = {hSig[wr], fc2a_w,      HQ, D_FC2_IN};
            GSeg b = {hS[wr],   fc2a_w + HQ, HS, D_FC2_IN};
            gemm_tc<<<dim3(D_FC2_H / 64, BB / 128), 256>>>(a, b, nil, 2, fc2a_b, nullptr,
                a2, D_FC2_H, 1, 0, nullptr, nullptr, 0);
        }

        // fc2b: k_vec = a2 @ fc2b_w^T + b
        {
            GSeg a = {a2, fc2b_w, D_FC2_H, D_FC2_H};
            gemm_tc<<<dim3(NN * MM / 64, BB / 128), 256>>>(a, nil, nil, 1, fc2b_b, nullptr,
                kvec, NN * MM, 0, 0, nullptr, nullptr, 0);
        }

        update_kernel<<<BB, 32>>>(x_prior, kvec, dy, out + (size_t)t * BB * MM);
    }
}

// round 5
// speedup vs baseline: 1.0080x; 1.0080x over previous
#include <cuda_runtime.h>
#include <cuda_bf16.h>
#include <math.h>
#include <stdint.h>

// ---------------- problem constants ----------------
#define MM   32      // state dim m
#define NN   16      // obs dim n
#define BB   256     // batch
#define TT   8       // time steps
#define HQ   1024    // m*m
#define HS   256     // n*n
#define D_Q_IN   160      // m*IN_MULT
#define D_SIG_IN 1184     // HQ + 160
#define D_S_IN   416      // 256 + 160
#define D_FC2_IN 1280     // HQ + HS
#define D_FC2_H  2560

// ---------------- device scratch (no allocations allowed) ----------------
__device__ float g_hQ  [2][BB * HQ];
__device__ float g_cQ  [BB * HQ];
__device__ float g_hSig[2][BB * HQ];
__device__ float g_cSig[BB * HQ];
__device__ float g_hS  [2][BB * HS];
__device__ float g_cS  [BB * HS];
__device__ float g_out5[BB * D_Q_IN];
__device__ float g_out6[BB * D_Q_IN];
__device__ float g_out7[BB * D_Q_IN];
__device__ float g_out1[BB * HS];
__device__ float g_a2  [BB * D_FC2_H];
__device__ float g_kvec[BB * NN * MM];
__device__ float g_xprior[2][BB * MM];
__device__ float g_dy   [BB * NN];
__device__ float g_yprev0[BB * NN];

__device__ __forceinline__ float sigmoidf(float x) { return 1.f / (1.f + expf(-x)); }

// ---------------- init: zero states, y_prev0 = tanh(x0[:, :16]) ----------------
__global__ void init_kernel(const float* __restrict__ x0, float* __restrict__ yprev0)
{
    int idx = blockIdx.x * blockDim.x + threadIdx.x;
    if (idx < BB * HQ) {
        g_hQ[0][idx] = 0.f; g_hQ[1][idx] = 0.f; g_cQ[idx] = 0.f;
        g_hSig[0][idx] = 0.f; g_hSig[1][idx] = 0.f; g_cSig[idx] = 0.f;
    }
    if (idx < BB * HS) { g_hS[0][idx] = 0.f; g_hS[1][idx] = 0.f; g_cS[idx] = 0.f; }
    if (idx < BB * NN) {
        int b = idx / NN, n = idx % NN;
        yprev0[idx] = tanhf(x0[b * MM + n]);
    }
}

// ---------------- fused prologue + fc5/6/7 ----------------
// grid = BB, block = 192 (warp 0 does features; all threads do the 3 small FCs)
__global__ void pre_fc_kernel(const float* __restrict__ x_post,
                              const float* __restrict__ x_post_prev,
                              const float* __restrict__ x_prior_prev,
                              const float* __restrict__ y_t,
                              const float* __restrict__ y_prev,
                              float* __restrict__ x_prior,
                              float* __restrict__ dy_buf,
                              const float* __restrict__ w5, const float* __restrict__ b5,
                              const float* __restrict__ w6, const float* __restrict__ b6,
                              const float* __restrict__ w7, const float* __restrict__ b7,
                              float* __restrict__ out5,
                              float* __restrict__ out6,
                              float* __restrict__ out7)
{
    int b = blockIdx.x;
    int tid = threadIdx.x;
    __shared__ float fwu[32], fwe[32], obs[32];

    if (tid < 32) {
        int lane = tid;
        float xp   = x_post[b * MM + lane];
        float xpp  = x_post_prev[b * MM + lane];
        float xprp = x_prior_prev[b * MM + lane];

        float xpr = xp + 0.1f * sinf(xp);
        x_prior[b * MM + lane] = xpr;

        float de = xp - xpp;
        float du = xp - xprp;
        float se = de * de, su = du * du;
        #pragma unroll
        for (int o = 16; o > 0; o >>= 1) {
            se += __shfl_xor_sync(0xffffffffu, se, o);
            su += __shfl_xor_sync(0xffffffffu, su, o);
        }
        fwe[lane] = de / fmaxf(sqrtf(se), 1e-12f);
        fwu[lane] = du / fmaxf(sqrtf(su), 1e-12f);

        float y     = (lane < NN) ? y_t[b * NN + lane]    : 0.f;
        float ypv   = (lane < NN) ? y_prev[b * NN + lane] : 0.f;
        float ypred = (lane < NN) ? tanhf(xpr)            : 0.f;
        float d1 = y - ypv;
        float d2 = y - ypred;
        if (lane < NN) dy_buf[b * NN + lane] = d2;
        float s1 = d1 * d1, s2 = d2 * d2;
        #pragma unroll
        for (int o = 16; o > 0; o >>= 1) {
            s1 += __shfl_xor_sync(0xffffffffu, s1, o);
            s2 += __shfl_xor_sync(0xffffffffu, s2, o);
        }
        if (lane < NN) {
            obs[lane]      = d1 / fmaxf(sqrtf(s1), 1e-12f);
            obs[NN + lane] = d2 / fmaxf(sqrtf(s2), 1e-12f);
        }
    }
    __syncthreads();

    for (int o = tid; o < 480; o += 192) {
        int which = o / 160, oo = o - which * 160;
        const float* W; const float* Bv; const float* xs; float* O;
        if (which == 0)      { W = w5; Bv = b5; xs = fwu; O = out5; }
        else if (which == 1) { W = w6; Bv = b6; xs = fwe; O = out6; }
        else                 { W = w7; Bv = b7; xs = obs; O = out7; }
        float acc = Bv[oo];
        const float* wr = W + oo * 32;
        #pragma unroll
        for (int k = 0; k < 32; k++) acc += xs[k] * wr[k];
        O[b * 160 + oo] = fmaxf(acc, 0.f);
    }
}

// ---------------- TF32 tensor-core multi-segment GEMM, 3-stage cp.async ----------------
// lstmH == 0: Z[b,o] = act( sum + bias0 (+bias1) )  — plain FC
// lstmH  > 0: gate-interleaved addressing. Logical output col rp maps to weight/bias
//             row ro = (rp&3)*lstmH + (rp>>2). Epilogue computes the LSTM cell
//             (c update + h output) in-register via lane pairing. No repacked weights.
struct GSeg {
    const float* X;   // [BB, K] contiguous
    const float* W;   // row-major, row stride ldw (may carry a column offset)
    int K;
    int ldw;
};

#define LDA 20   // padded smem stride

__device__ __forceinline__ void cpa16(void* s, const void* g) {
    uint32_t sa = (uint32_t)__cvta_generic_to_shared(s);
    asm volatile("cp.async.cg.shared.global [%0], [%1], 16;\n" :: "r"(sa), "l"(g));
}
__device__ __forceinline__ uint32_t f2tf32(float f) {
    uint32_t u;
    asm("cvt.rna.tf32.f32 %0, %1;" : "=r"(u) : "f"(f));
    return u;
}

__global__ void __launch_bounds__(256) gemm_tc(
    GSeg s0, GSeg s1, GSeg s2, int nseg,
    const float* __restrict__ bias0, const float* __restrict__ bias1,
    float* __restrict__ Z, int Nout, int act,
    int lstmH, float* __restrict__ cst, float* __restrict__ hout)
{
    __shared__ float As[3][128 * LDA];
    __shared__ float Bs[3][64 * LDA];

    int tid  = threadIdx.x;
    int lane = tid & 31;
    int wid  = tid >> 5;
    int wm   = wid & 3;
    int wn   = wid >> 2;
    int gid  = lane >> 2;
    int tg   = lane & 3;

    int row0 = blockIdx.y * 128;
    int col0 = blockIdx.x * 64;

    int arow = tid >> 2;
    int acol = (tid & 3) * 4;

    // B-tile row mapping: logical col -> weight row (gate interleave for LSTM)
    int bc = col0 + arow;
    int brow_g = lstmH ? ((bc & 3) * lstmH + (bc >> 2)) : bc;

    int totK = s0.K + ((nseg > 1) ? s1.K : 0) + ((nseg > 2) ? s2.K : 0);
    int niter = totK >> 4;

    float c[2][4][4];
    #pragma unroll
    for (int mt = 0; mt < 2; mt++)
        #pragma unroll
        for (int nt = 0; nt < 4; nt++)
            #pragma unroll
            for (int r = 0; r < 4; r++) c[mt][nt][r] = 0.f;

    auto issue = [&](int it, int p) {
        int kb = it << 4;
        const float* X = s0.X; const float* W = s0.W; int K = s0.K; int ldw = s0.ldw;
        if (kb >= s0.K) {
            kb -= s0.K;
            if (nseg > 2 && kb >= s1.K) { kb -= s1.K; X = s2.X; W = s2.W; K = s2.K; ldw = s2.ldw; }
            else                        {             X = s1.X; W = s1.W; K = s1.K; ldw = s1.ldw; }
        }
        const float* xsrc = X + (size_t)(row0 + arow) * K + kb + acol;
        cpa16(&As[p][arow * LDA + acol],        xsrc);
        cpa16(&As[p][(arow + 64) * LDA + acol], xsrc + (size_t)64 * K);
        cpa16(&Bs[p][arow * LDA + acol],
              W + (size_t)brow_g * ldw + kb + acol);
        asm volatile("cp.async.commit_group;\n" ::);
    };

    issue(0, 0);
    if (niter > 1) issue(1, 1);

    for (int it = 0; it < niter; it++) {
        int p = it % 3;
        if (it < niter - 1) {
            asm volatile("cp.async.wait_group 1;\n" ::);
        } else {
            asm volatile("cp.async.wait_group 0;\n" ::);
        }
        __syncthreads();
        if (it + 2 < niter) issue(it + 2, (it + 2) % 3);

        #pragma unroll
        for (int ks = 0; ks < 2; ks++) {
            int kk = ks * 8;
            uint32_t af[2][4];
            #pragma unroll
            for (int mt = 0; mt < 2; mt++) {
                int r = wm * 32 + mt * 16 + gid;
                af[mt][0] = f2tf32(As[p][r * LDA + kk + tg]);
                af[mt][1] = f2tf32(As[p][(r + 8) * LDA + kk + tg]);
                af[mt][2] = f2tf32(As[p][r * LDA + kk + tg + 4]);
                af[mt][3] = f2tf32(As[p][(r + 8) * LDA + kk + tg + 4]);
            }
            uint32_t bf[4][2];
            #pragma unroll
            for (int nt = 0; nt < 4; nt++) {
                int n = wn * 32 + nt * 8 + gid;
                bf[nt][0] = f2tf32(Bs[p][n * LDA + kk + tg]);
                bf[nt][1] = f2tf32(Bs[p][n * LDA + kk + tg + 4]);
            }
            #pragma unroll
            for (int mt = 0; mt < 2; mt++)
                #pragma unroll
                for (int nt = 0; nt < 4; nt++) {
                    asm volatile(
                        "mma.sync.aligned.m16n8k8.row.col.f32.tf32.tf32.f32 "
                        "{%0,%1,%2,%3}, {%4,%5,%6,%7}, {%8,%9}, {%0,%1,%2,%3};\n"
                        : "+f"(c[mt][nt][0]), "+f"(c[mt][nt][1]),
                          "+f"(c[mt][nt][2]), "+f"(c[mt][nt][3])
                        : "r"(af[mt][0]), "r"(af[mt][1]), "r"(af[mt][2]), "r"(af[mt][3]),
                          "r"(bf[nt][0]), "r"(bf[nt][1]));
                }
        }
        __syncthreads();
    }

    if (lstmH == 0) {
        #pragma unroll
        for (int mt = 0; mt < 2; mt++) {
            int r = row0 + wm * 32 + mt * 16 + gid;
            #pragma unroll
            for (int nt = 0; nt < 4; nt++) {
                int cb = col0 + wn * 32 + nt * 8 + tg * 2;
                float b0a = bias0[cb], b0b = bias0[cb + 1];
                if (bias1) { b0a += bias1[cb]; b0b += bias1[cb + 1]; }
                float v0 = c[mt][nt][0] + b0a;
                float v1 = c[mt][nt][1] + b0b;
                float v2 = c[mt][nt][2] + b0a;
                float v3 = c[mt][nt][3] + b0b;
                if (act) {
                    v0 = fmaxf(v0, 0.f); v1 = fmaxf(v1, 0.f);
                    v2 = fmaxf(v2, 0.f); v3 = fmaxf(v3, 0.f);
                }
                *reinterpret_cast<float2*>(&Z[(size_t)r * Nout + cb])       = make_float2(v0, v1);
                *reinterpret_cast<float2*>(&Z[(size_t)(r + 8) * Nout + cb]) = make_float2(v2, v3);
            }
        }
    } else {
        // fused LSTM cell: lane tg even holds (i,f) of unit j, lane tg^1 holds (g,o)
        const int H = lstmH;
        #pragma unroll
        for (int mt = 0; mt < 2; mt++) {
            int r = row0 + wm * 32 + mt * 16 + gid;
            #pragma unroll
            for (int nt = 0; nt < 4; nt++) {
                int cb = col0 + wn * 32 + nt * 8 + tg * 2;   // logical col (j*4+g)
                int ro0 = (cb & 3) * H + (cb >> 2);
                int ro1 = ((cb + 1) & 3) * H + ((cb + 1) >> 2);
                float b0a = bias0[ro0] + bias1[ro0];
                float b0b = bias0[ro1] + bias1[ro1];
                float z0 = c[mt][nt][0] + b0a;
                float z1 = c[mt][nt][1] + b0b;
                float z2 = c[mt][nt][2] + b0a;
                float z3 = c[mt][nt][3] + b0b;
                float p0 = __shfl_xor_sync(0xffffffffu, z0, 1);
                float p1 = __shfl_xor_sync(0xffffffffu, z1, 1);
                float p2 = __shfl_xor_sync(0xffffffffu, z2, 1);
                float p3 = __shfl_xor_sync(0xffffffffu, z3, 1);
                if ((tg & 1) == 0) {
                    int jj = cb >> 2;
                    {
                        float si = sigmoidf(z0), sf = sigmoidf(z1);
                        float gg = tanhf(p0),    so = sigmoidf(p1);
                        float cn = sf * cst[(size_t)r * H + jj] + si * gg;
                        cst[(size_t)r * H + jj] = cn;
                        hout[(size_t)r * H + jj] = so * tanhf(cn);
                    }
                    {
                        float si = sigmoidf(z2), sf = sigmoidf(z3);
                        float gg = tanhf(p2),    so = sigmoidf(p3);
                        float cn = sf * cst[(size_t)(r + 8) * H + jj] + si * gg;
                        cst[(size_t)(r + 8) * H + jj] = cn;
                        hout[(size_t)(r + 8) * H + jj] = so * tanhf(cn);
                    }
                }
            }
        }
    }
}

// ---------------- KF update: x_post = x_prior + K @ dy ----------------
__global__ void update_kernel(const float* __restrict__ x_prior,
                              const float* __restrict__ kvec,
                              const float* __restrict__ dy,
                              float* __restrict__ out)
{
    int b = blockIdx.x;
    int m = threadIdx.x;
    __shared__ float dys[NN];
    if (m < NN) dys[m] = dy[b * NN + m];
    __syncthreads();
    float acc = x_prior[b * MM + m];
    const float* Kr = kvec + (size_t)b * MM * NN + m * NN;
    #pragma unroll
    for (int n = 0; n < NN; n++) acc += Kr[n] * dys[n];
    out[b * MM + m] = acc;
}

// ---------------- host orchestration ----------------
extern "C" void kernel_launch(void* const* d_in, const int* in_sizes, int n_in,
                              void* d_out, int out_size)
{
    const float* Y       = (const float*)d_in[0];
    const float* x0      = (const float*)d_in[1];
    const float* Wq_ih   = (const float*)d_in[2];
    const float* Wq_hh   = (const float*)d_in[3];
    const float* bq_ih   = (const float*)d_in[4];
    const float* bq_hh   = (const float*)d_in[5];
    const float* Wsig_ih = (const float*)d_in[6];
    const float* Wsig_hh = (const float*)d_in[7];
    const float* bsig_ih = (const float*)d_in[8];
    const float* bsig_hh = (const float*)d_in[9];
    const float* Ws_ih   = (const float*)d_in[10];
    const float* Ws_hh   = (const float*)d_in[11];
    const float* bs_ih   = (const float*)d_in[12];
    const float* bs_hh   = (const float*)d_in[13];
    const float* fc1_w   = (const float*)d_in[14];
    const float* fc1_b   = (const float*)d_in[15];
    const float* fc2a_w  = (const float*)d_in[16];
    const float* fc2a_b  = (const float*)d_in[17];
    const float* fc2b_w  = (const float*)d_in[18];
    const float* fc2b_b  = (const float*)d_in[19];
    const float* fc5_w   = (const float*)d_in[20];
    const float* fc5_b   = (const float*)d_in[21];
    const float* fc6_w   = (const float*)d_in[22];
    const float* fc6_b   = (const float*)d_in[23];
    const float* fc7_w   = (const float*)d_in[24];
    const float* fc7_b   = (const float*)d_in[25];

    float* out = (float*)d_out;   // [T, B, M, 1]

    float *hQ0, *cQ, *hSig0, *cSig, *hS0, *cS;
    float *out5, *out6, *out7, *out1, *a2, *kvec;
    float *xprior0, *dy, *yprev0;
    cudaGetSymbolAddress((void**)&hQ0,   g_hQ);
    cudaGetSymbolAddress((void**)&cQ,    g_cQ);
    cudaGetSymbolAddress((void**)&hSig0, g_hSig);
    cudaGetSymbolAddress((void**)&cSig,  g_cSig);
    cudaGetSymbolAddress((void**)&hS0,   g_hS);
    cudaGetSymbolAddress((void**)&cS,    g_cS);
    cudaGetSymbolAddress((void**)&out5,  g_out5);
    cudaGetSymbolAddress((void**)&out6,  g_out6);
    cudaGetSymbolAddress((void**)&out7,  g_out7);
    cudaGetSymbolAddress((void**)&out1,  g_out1);
    cudaGetSymbolAddress((void**)&a2,    g_a2);
    cudaGetSymbolAddress((void**)&kvec,  g_kvec);
    cudaGetSymbolAddress((void**)&xprior0, g_xprior);
    cudaGetSymbolAddress((void**)&dy,    g_dy);
    cudaGetSymbolAddress((void**)&yprev0,g_yprev0);

    float* hQ[2]   = {hQ0,   hQ0   + BB * HQ};
    float* hSig[2] = {hSig0, hSig0 + BB * HQ};
    float* hS[2]   = {hS0,   hS0   + BB * HS};
    float* xprior_buf[2] = {xprior0, xprior0 + BB * MM};

    const GSeg nil = {nullptr, nullptr, 0, 0};

    init_kernel<<<(BB * HQ + 255) / 256, 256>>>(x0, yprev0);

    for (int t = 0; t < TT; t++) {
        const float* x_post      = (t == 0) ? x0 : out + (size_t)(t - 1) * BB * MM;
        const float* x_post_prev = (t <= 1) ? x0 : out + (size_t)(t - 2) * BB * MM;
        const float* x_prior_prev= (t == 0) ? x0 : xprior_buf[(t - 1) & 1];
        const float* y_t         = Y + (size_t)t * BB * NN;
        const float* y_prev      = (t == 0) ? yprev0 : Y + (size_t)(t - 1) * BB * NN;
        float* x_prior           = xprior_buf[t & 1];
        int rd = t & 1, wr = rd ^ 1;

        pre_fc_kernel<<<BB, 192>>>(x_post, x_post_prev, x_prior_prev, y_t, y_prev,
                                   x_prior, dy,
                                   fc5_w, fc5_b, fc6_w, fc6_b, fc7_w, fc7_b,
                                   out5, out6, out7);

        // LSTM Q (fused cell epilogue, gate-interleaved addressing on original weights)
        {
            GSeg a = {out5,   Wq_ih, D_Q_IN, D_Q_IN};
            GSeg b = {hQ[rd], Wq_hh, HQ,     HQ};
            gemm_tc<<<dim3(4 * HQ / 64, BB / 128), 256>>>(a, b, nil, 2, bq_ih, bq_hh,
                nullptr, 0, 0, HQ, cQ, hQ[wr]);
        }

        // LSTM Sigma: input = concat(hQ_new, out6)
        {
            GSeg a = {hQ[wr],   Wsig_ih,        HQ,     D_SIG_IN};
            GSeg b = {out6,     Wsig_ih + HQ,   D_Q_IN, D_SIG_IN};
            GSeg c = {hSig[rd], Wsig_hh,        HQ,     HQ};
            gemm_tc<<<dim3(4 * HQ / 64, BB / 128), 256>>>(a, b, c, 3, bsig_ih, bsig_hh,
                nullptr, 0, 0, HQ, cSig, hSig[wr]);
        }

        // fc1: relu(hSig_new @ fc1_w^T + b)
        {
            GSeg a = {hSig[wr], fc1_w, HQ, HQ};
            gemm_tc<<<dim3(HS / 64, BB / 128), 256>>>(a, nil, nil, 1, fc1_b, nullptr,
                out1, HS, 1, 0, nullptr, nullptr);
        }

        // LSTM S: input = concat(out1, out7)
        {
            GSeg a = {out1,   Ws_ih,       HS,     D_S_IN};
            GSeg b = {out7,   Ws_ih + HS,  D_Q_IN, D_S_IN};
            GSeg c = {hS[rd], Ws_hh,       HS,     HS};
            gemm_tc<<<dim3(4 * HS / 64, BB / 128), 256>>>(a, b, c, 3, bs_ih, bs_hh,
                nullptr, 0, 0, HS, cS, hS[wr]);
        }

        // fc2a: relu(concat(hSig_new, hS_new) @ fc2a_w^T + b)
        {
            GSeg a = {hSig[wr], fc2a_w,      HQ, D_FC2_IN};
            GSeg b = {hS[wr],   fc2a_w + HQ, HS, D_FC2_IN};
            gemm_tc<<<dim3(D_FC2_H / 64, BB / 128), 256>>>(a, b, nil, 2, fc2a_b, nullptr,
                a2, D_FC2_H, 1, 0, nullptr, nullptr);
        }

        // fc2b: k_vec = a2 @ fc2b_w^T + b
        {
            GSeg a = {a2, fc2b_w, D_FC2_H, D_FC2_H};
            gemm_tc<<<dim3(NN * MM / 64, BB / 128), 256>>>(a, nil, nil, 1, fc2b_b, nullptr,
                kvec, NN * MM, 0, 0, nullptr, nullptr);
        }

        update_kernel<<<BB, 32>>>(x_prior, kvec, dy, out + (size_t)t * BB * MM);
    }
}

// round 6
// speedup vs baseline: 1.5623x; 1.5499x over previous
#include <cuda_runtime.h>
#include <cuda_bf16.h>
#include <math.h>
#include <stdint.h>

// ---------------- problem constants ----------------
#define MM   32      // state dim m
#define NN   16      // obs dim n
#define BB   256     // batch
#define TT   8       // time steps
#define HQ   1024    // m*m
#define HS   256     // n*n
#define D_Q_IN   160      // m*IN_MULT
#define D_SIG_IN 1184     // HQ + 160
#define D_S_IN   416      // 256 + 160
#define D_FC2_IN 1280     // HQ + HS
#define D_FC2_H  2560

// ---------------- device scratch (no allocations allowed) ----------------
__device__ float g_hQ  [2][BB * HQ];
__device__ float g_cQ  [BB * HQ];
__device__ float g_hSig[2][BB * HQ];
__device__ float g_cSig[BB * HQ];
__device__ float g_hS  [2][BB * HS];
__device__ float g_cS  [BB * HS];
__device__ float g_out5[BB * D_Q_IN];
__device__ float g_out6[BB * D_Q_IN];
__device__ float g_out7[BB * D_Q_IN];
__device__ float g_out1[BB * HS];
__device__ float g_a2  [BB * D_FC2_H];
__device__ float g_kvec[BB * NN * MM];
__device__ float g_xprior[2][BB * MM];
__device__ float g_dy   [BB * NN];
__device__ float g_yprev0[BB * NN];

__device__ __forceinline__ float sigmoidf(float x) { return 1.f / (1.f + expf(-x)); }

// ---------------- init: zero states, y_prev0 = tanh(x0[:, :16]) ----------------
__global__ void init_kernel(const float* __restrict__ x0, float* __restrict__ yprev0)
{
    int idx = blockIdx.x * blockDim.x + threadIdx.x;
    if (idx < BB * HQ) {
        g_hQ[0][idx] = 0.f; g_hQ[1][idx] = 0.f; g_cQ[idx] = 0.f;
        g_hSig[0][idx] = 0.f; g_hSig[1][idx] = 0.f; g_cSig[idx] = 0.f;
    }
    if (idx < BB * HS) { g_hS[0][idx] = 0.f; g_hS[1][idx] = 0.f; g_cS[idx] = 0.f; }
    if (idx < BB * NN) {
        int b = idx / NN, n = idx % NN;
        yprev0[idx] = tanhf(x0[b * MM + n]);
    }
}

// ---------------- fused prologue + fc5/6/7 ----------------
__global__ void pre_fc_kernel(const float* __restrict__ x_post,
                              const float* __restrict__ x_post_prev,
                              const float* __restrict__ x_prior_prev,
                              const float* __restrict__ y_t,
                              const float* __restrict__ y_prev,
                              float* __restrict__ x_prior,
                              float* __restrict__ dy_buf,
                              const float* __restrict__ w5, const float* __restrict__ b5,
                              const float* __restrict__ w6, const float* __restrict__ b6,
                              const float* __restrict__ w7, const float* __restrict__ b7,
                              float* __restrict__ out5,
                              float* __restrict__ out6,
                              float* __restrict__ out7)
{
    int b = blockIdx.x;
    int tid = threadIdx.x;
    __shared__ float fwu[32], fwe[32], obs[32];

    if (tid < 32) {
        int lane = tid;
        float xp   = x_post[b * MM + lane];
        float xpp  = x_post_prev[b * MM + lane];
        float xprp = x_prior_prev[b * MM + lane];

        float xpr = xp + 0.1f * sinf(xp);
        x_prior[b * MM + lane] = xpr;

        float de = xp - xpp;
        float du = xp - xprp;
        float se = de * de, su = du * du;
        #pragma unroll
        for (int o = 16; o > 0; o >>= 1) {
            se += __shfl_xor_sync(0xffffffffu, se, o);
            su += __shfl_xor_sync(0xffffffffu, su, o);
        }
        fwe[lane] = de / fmaxf(sqrtf(se), 1e-12f);
        fwu[lane] = du / fmaxf(sqrtf(su), 1e-12f);

        float y     = (lane < NN) ? y_t[b * NN + lane]    : 0.f;
        float ypv   = (lane < NN) ? y_prev[b * NN + lane] : 0.f;
        float ypred = (lane < NN) ? tanhf(xpr)            : 0.f;
        float d1 = y - ypv;
        float d2 = y - ypred;
        if (lane < NN) dy_buf[b * NN + lane] = d2;
        float s1 = d1 * d1, s2 = d2 * d2;
        #pragma unroll
        for (int o = 16; o > 0; o >>= 1) {
            s1 += __shfl_xor_sync(0xffffffffu, s1, o);
            s2 += __shfl_xor_sync(0xffffffffu, s2, o);
        }
        if (lane < NN) {
            obs[lane]      = d1 / fmaxf(sqrtf(s1), 1e-12f);
            obs[NN + lane] = d2 / fmaxf(sqrtf(s2), 1e-12f);
        }
    }
    __syncthreads();

    for (int o = tid; o < 480; o += 192) {
        int which = o / 160, oo = o - which * 160;
        const float* W; const float* Bv; const float* xs; float* O;
        if (which == 0)      { W = w5; Bv = b5; xs = fwu; O = out5; }
        else if (which == 1) { W = w6; Bv = b6; xs = fwe; O = out6; }
        else                 { W = w7; Bv = b7; xs = obs; O = out7; }
        float acc = Bv[oo];
        const float* wr = W + oo * 32;
        #pragma unroll
        for (int k = 0; k < 32; k++) acc += xs[k] * wr[k];
        O[b * 160 + oo] = fmaxf(acc, 0.f);
    }
}

// ---------------- TF32 tensor-core multi-segment GEMM ----------------
// Tiles: BM=64 BN=64 BK=32, 128 threads (4 warps, 2x2), 2-stage cp.async.
// lstmH==0: Z = act(sum + bias0 (+bias1)).
// lstmH >0: gate-interleaved weight addressing (col rp -> row (rp&3)*H + (rp>>2));
//           epilogue computes LSTM cell (c,h) in-register via lane pairing.
struct GSeg {
    const float* X;   // [BB, K] contiguous
    const float* W;   // row-major, row stride ldw (may carry a column offset)
    int K;
    int ldw;
};

#define LDA 36   // padded smem stride for BK=32

__device__ __forceinline__ void cpa16(void* s, const void* g) {
    uint32_t sa = (uint32_t)__cvta_generic_to_shared(s);
    asm volatile("cp.async.cg.shared.global [%0], [%1], 16;\n" :: "r"(sa), "l"(g));
}
__device__ __forceinline__ uint32_t f2tf32(float f) {
    uint32_t u;
    asm("cvt.rna.tf32.f32 %0, %1;" : "=r"(u) : "f"(f));
    return u;
}

__global__ void __launch_bounds__(128) gemm_tc(
    GSeg s0, GSeg s1, GSeg s2, int nseg,
    const float* __restrict__ bias0, const float* __restrict__ bias1,
    float* __restrict__ Z, int Nout, int act,
    int lstmH, float* __restrict__ cst, float* __restrict__ hout)
{
    __shared__ float As[2][64 * LDA];
    __shared__ float Bs[2][64 * LDA];

    int tid  = threadIdx.x;
    int lane = tid & 31;
    int wid  = tid >> 5;
    int wm   = wid & 1;      // warp m (0..1)
    int wn   = wid >> 1;     // warp n (0..1)
    int gid  = lane >> 2;    // 0..7
    int tg   = lane & 3;     // 0..3

    int row0 = blockIdx.y * 64;
    int col0 = blockIdx.x * 64;

    // staging: each thread loads 4 rows (srow + 16*i), 16B each
    int srow = tid >> 3;          // 0..15
    int scol = (tid & 7) * 4;     // 0..28

    // B row mapping (gate interleave for LSTM)
    int brow_g[4];
    #pragma unroll
    for (int i = 0; i < 4; i++) {
        int bc = col0 + srow + 16 * i;
        brow_g[i] = lstmH ? ((bc & 3) * lstmH + (bc >> 2)) : bc;
    }

    int totK = s0.K + ((nseg > 1) ? s1.K : 0) + ((nseg > 2) ? s2.K : 0);
    int niter = totK >> 5;

    float c[2][4][4];
    #pragma unroll
    for (int mt = 0; mt < 2; mt++)
        #pragma unroll
        for (int nt = 0; nt < 4; nt++)
            #pragma unroll
            for (int r = 0; r < 4; r++) c[mt][nt][r] = 0.f;

    auto issue = [&](int it, int p) {
        int kb = it << 5;
        const float* X = s0.X; const float* W = s0.W; int K = s0.K; int ldw = s0.ldw;
        if (kb >= s0.K) {
            kb -= s0.K;
            if (nseg > 2 && kb >= s1.K) { kb -= s1.K; X = s2.X; W = s2.W; K = s2.K; ldw = s2.ldw; }
            else                        {             X = s1.X; W = s1.W; K = s1.K; ldw = s1.ldw; }
        }
        #pragma unroll
        for (int i = 0; i < 4; i++) {
            int r = srow + 16 * i;
            cpa16(&As[p][r * LDA + scol], X + (size_t)(row0 + r) * K + kb + scol);
            cpa16(&Bs[p][r * LDA + scol], W + (size_t)brow_g[i] * ldw + kb + scol);
        }
        asm volatile("cp.async.commit_group;\n" ::);
    };

    issue(0, 0);

    for (int it = 0; it < niter; it++) {
        int p = it & 1;
        if (it + 1 < niter) {
            issue(it + 1, p ^ 1);
            asm volatile("cp.async.wait_group 1;\n" ::);
        } else {
            asm volatile("cp.async.wait_group 0;\n" ::);
        }
        __syncthreads();

        #pragma unroll
        for (int ks = 0; ks < 4; ks++) {
            int kk = ks * 8;
            uint32_t af[2][4];
            #pragma unroll
            for (int mt = 0; mt < 2; mt++) {
                int r = wm * 32 + mt * 16 + gid;
                af[mt][0] = f2tf32(As[p][r * LDA + kk + tg]);
                af[mt][1] = f2tf32(As[p][(r + 8) * LDA + kk + tg]);
                af[mt][2] = f2tf32(As[p][r * LDA + kk + tg + 4]);
                af[mt][3] = f2tf32(As[p][(r + 8) * LDA + kk + tg + 4]);
            }
            uint32_t bf[4][2];
            #pragma unroll
            for (int nt = 0; nt < 4; nt++) {
                int n = wn * 32 + nt * 8 + gid;
                bf[nt][0] = f2tf32(Bs[p][n * LDA + kk + tg]);
                bf[nt][1] = f2tf32(Bs[p][n * LDA + kk + tg + 4]);
            }
            #pragma unroll
            for (int mt = 0; mt < 2; mt++)
                #pragma unroll
                for (int nt = 0; nt < 4; nt++) {
                    asm volatile(
                        "mma.sync.aligned.m16n8k8.row.col.f32.tf32.tf32.f32 "
                        "{%0,%1,%2,%3}, {%4,%5,%6,%7}, {%8,%9}, {%0,%1,%2,%3};\n"
                        : "+f"(c[mt][nt][0]), "+f"(c[mt][nt][1]),
                          "+f"(c[mt][nt][2]), "+f"(c[mt][nt][3])
                        : "r"(af[mt][0]), "r"(af[mt][1]), "r"(af[mt][2]), "r"(af[mt][3]),
                          "r"(bf[nt][0]), "r"(bf[nt][1]));
                }
        }
        __syncthreads();
    }

    if (lstmH == 0) {
        #pragma unroll
        for (int mt = 0; mt < 2; mt++) {
            int r = row0 + wm * 32 + mt * 16 + gid;
            #pragma unroll
            for (int nt = 0; nt < 4; nt++) {
                int cb = col0 + wn * 32 + nt * 8 + tg * 2;
                float b0a = bias0[cb], b0b = bias0[cb + 1];
                if (bias1) { b0a += bias1[cb]; b0b += bias1[cb + 1]; }
                float v0 = c[mt][nt][0] + b0a;
                float v1 = c[mt][nt][1] + b0b;
                float v2 = c[mt][nt][2] + b0a;
                float v3 = c[mt][nt][3] + b0b;
                if (act) {
                    v0 = fmaxf(v0, 0.f); v1 = fmaxf(v1, 0.f);
                    v2 = fmaxf(v2, 0.f); v3 = fmaxf(v3, 0.f);
                }
                *reinterpret_cast<float2*>(&Z[(size_t)r * Nout + cb])       = make_float2(v0, v1);
                *reinterpret_cast<float2*>(&Z[(size_t)(r + 8) * Nout + cb]) = make_float2(v2, v3);
            }
        }
    } else {
        const int H = lstmH;
        #pragma unroll
        for (int mt = 0; mt < 2; mt++) {
            int r = row0 + wm * 32 + mt * 16 + gid;
            #pragma unroll
            for (int nt = 0; nt < 4; nt++) {
                int cb = col0 + wn * 32 + nt * 8 + tg * 2;   // logical col (j*4+g)
                int ro0 = (cb & 3) * H + (cb >> 2);
                int ro1 = ((cb + 1) & 3) * H + ((cb + 1) >> 2);
                float b0a = bias0[ro0] + bias1[ro0];
                float b0b = bias0[ro1] + bias1[ro1];
                float z0 = c[mt][nt][0] + b0a;
                float z1 = c[mt][nt][1] + b0b;
                float z2 = c[mt][nt][2] + b0a;
                float z3 = c[mt][nt][3] + b0b;
                float p0 = __shfl_xor_sync(0xffffffffu, z0, 1);
                float p1 = __shfl_xor_sync(0xffffffffu, z1, 1);
                float p2 = __shfl_xor_sync(0xffffffffu, z2, 1);
                float p3 = __shfl_xor_sync(0xffffffffu, z3, 1);
                if ((tg & 1) == 0) {
                    int jj = cb >> 2;
                    {
                        float si = sigmoidf(z0), sf = sigmoidf(z1);
                        float gg = tanhf(p0),    so = sigmoidf(p1);
                        float cn = sf * cst[(size_t)r * H + jj] + si * gg;
                        cst[(size_t)r * H + jj] = cn;
                        hout[(size_t)r * H + jj] = so * tanhf(cn);
                    }
                    {
                        float si = sigmoidf(z2), sf = sigmoidf(z3);
                        float gg = tanhf(p2),    so = sigmoidf(p3);
                        float cn = sf * cst[(size_t)(r + 8) * H + jj] + si * gg;
                        cst[(size_t)(r + 8) * H + jj] = cn;
                        hout[(size_t)(r + 8) * H + jj] = so * tanhf(cn);
                    }
                }
            }
        }
    }
}

// ---------------- KF update: x_post = x_prior + K @ dy ----------------
__global__ void update_kernel(const float* __restrict__ x_prior,
                              const float* __restrict__ kvec,
                              const float* __restrict__ dy,
                              float* __restrict__ out)
{
    int b = blockIdx.x;
    int m = threadIdx.x;
    __shared__ float dys[NN];
    if (m < NN) dys[m] = dy[b * NN + m];
    __syncthreads();
    float acc = x_prior[b * MM + m];
    const float* Kr = kvec + (size_t)b * MM * NN + m * NN;
    #pragma unroll
    for (int n = 0; n < NN; n++) acc += Kr[n] * dys[n];
    out[b * MM + m] = acc;
}

// ---------------- host orchestration ----------------
extern "C" void kernel_launch(void* const* d_in, const int* in_sizes, int n_in,
                              void* d_out, int out_size)
{
    const float* Y       = (const float*)d_in[0];
    const float* x0      = (const float*)d_in[1];
    const float* Wq_ih   = (const float*)d_in[2];
    const float* Wq_hh   = (const float*)d_in[3];
    const float* bq_ih   = (const float*)d_in[4];
    const float* bq_hh   = (const float*)d_in[5];
    const float* Wsig_ih = (const float*)d_in[6];
    const float* Wsig_hh = (const float*)d_in[7];
    const float* bsig_ih = (const float*)d_in[8];
    const float* bsig_hh = (const float*)d_in[9];
    const float* Ws_ih   = (const float*)d_in[10];
    const float* Ws_hh   = (const float*)d_in[11];
    const float* bs_ih   = (const float*)d_in[12];
    const float* bs_hh   = (const float*)d_in[13];
    const float* fc1_w   = (const float*)d_in[14];
    const float* fc1_b   = (const float*)d_in[15];
    const float* fc2a_w  = (const float*)d_in[16];
    const float* fc2a_b  = (const float*)d_in[17];
    const float* fc2b_w  = (const float*)d_in[18];
    const float* fc2b_b  = (const float*)d_in[19];
    const float* fc5_w   = (const float*)d_in[20];
    const float* fc5_b   = (const float*)d_in[21];
    const float* fc6_w   = (const float*)d_in[22];
    const float* fc6_b   = (const float*)d_in[23];
    const float* fc7_w   = (const float*)d_in[24];
    const float* fc7_b   = (const float*)d_in[25];

    float* out = (float*)d_out;   // [T, B, M, 1]

    float *hQ0, *cQ, *hSig0, *cSig, *hS0, *cS;
    float *out5, *out6, *out7, *out1, *a2, *kvec;
    float *xprior0, *dy, *yprev0;
    cudaGetSymbolAddress((void**)&hQ0,   g_hQ);
    cudaGetSymbolAddress((void**)&cQ,    g_cQ);
    cudaGetSymbolAddress((void**)&hSig0, g_hSig);
    cudaGetSymbolAddress((void**)&cSig,  g_cSig);
    cudaGetSymbolAddress((void**)&hS0,   g_hS);
    cudaGetSymbolAddress((void**)&cS,    g_cS);
    cudaGetSymbolAddress((void**)&out5,  g_out5);
    cudaGetSymbolAddress((void**)&out6,  g_out6);
    cudaGetSymbolAddress((void**)&out7,  g_out7);
    cudaGetSymbolAddress((void**)&out1,  g_out1);
    cudaGetSymbolAddress((void**)&a2,    g_a2);
    cudaGetSymbolAddress((void**)&kvec,  g_kvec);
    cudaGetSymbolAddress((void**)&xprior0, g_xprior);
    cudaGetSymbolAddress((void**)&dy,    g_dy);
    cudaGetSymbolAddress((void**)&yprev0,g_yprev0);

    float* hQ[2]   = {hQ0,   hQ0   + BB * HQ};
    float* hSig[2] = {hSig0, hSig0 + BB * HQ};
    float* hS[2]   = {hS0,   hS0   + BB * HS};
    float* xprior_buf[2] = {xprior0, xprior0 + BB * MM};

    const GSeg nil = {nullptr, nullptr, 0, 0};

    init_kernel<<<(BB * HQ + 255) / 256, 256>>>(x0, yprev0);

    for (int t = 0; t < TT; t++) {
        const float* x_post      = (t == 0) ? x0 : out + (size_t)(t - 1) * BB * MM;
        const float* x_post_prev = (t <= 1) ? x0 : out + (size_t)(t - 2) * BB * MM;
        const float* x_prior_prev= (t == 0) ? x0 : xprior_buf[(t - 1) & 1];
        const float* y_t         = Y + (size_t)t * BB * NN;
        const float* y_prev      = (t == 0) ? yprev0 : Y + (size_t)(t - 1) * BB * NN;
        float* x_prior           = xprior_buf[t & 1];
        int rd = t & 1, wr = rd ^ 1;

        pre_fc_kernel<<<BB, 192>>>(x_post, x_post_prev, x_prior_prev, y_t, y_prev,
                                   x_prior, dy,
                                   fc5_w, fc5_b, fc6_w, fc6_b, fc7_w, fc7_b,
                                   out5, out6, out7);

        // LSTM Q (fused cell epilogue, gate-interleaved addressing on original weights)
        {
            GSeg a = {out5,   Wq_ih, D_Q_IN, D_Q_IN};
            GSeg b = {hQ[rd], Wq_hh, HQ,     HQ};
            gemm_tc<<<dim3(4 * HQ / 64, BB / 64), 128>>>(a, b, nil, 2, bq_ih, bq_hh,
                nullptr, 0, 0, HQ, cQ, hQ[wr]);
        }

        // LSTM Sigma: input = concat(hQ_new, out6)
        {
            GSeg a = {hQ[wr],   Wsig_ih,        HQ,     D_SIG_IN};
            GSeg b = {out6,     Wsig_ih + HQ,   D_Q_IN, D_SIG_IN};
            GSeg c = {hSig[rd], Wsig_hh,        HQ,     HQ};
            gemm_tc<<<dim3(4 * HQ / 64, BB / 64), 128>>>(a, b, c, 3, bsig_ih, bsig_hh,
                nullptr, 0, 0, HQ, cSig, hSig[wr]);
        }

        // fc1: relu(hSig_new @ fc1_w^T + b)
        {
            GSeg a = {hSig[wr], fc1_w, HQ, HQ};
            gemm_tc<<<dim3(HS / 64, BB / 64), 128>>>(a, nil, nil, 1, fc1_b, nullptr,
                out1, HS, 1, 0, nullptr, nullptr);
        }

        // LSTM S: input = concat(out1, out7)
        {
            GSeg a = {out1,   Ws_ih,       HS,     D_S_IN};
            GSeg b = {out7,   Ws_ih + HS,  D_Q_IN, D_S_IN};
            GSeg c = {hS[rd], Ws_hh,       HS,     HS};
            gemm_tc<<<dim3(4 * HS / 64, BB / 64), 128>>>(a, b, c, 3, bs_ih, bs_hh,
                nullptr, 0, 0, HS, cS, hS[wr]);
        }

        // fc2a: relu(concat(hSig_new, hS_new) @ fc2a_w^T + b)
        {
            GSeg a = {hSig[wr], fc2a_w,      HQ, D_FC2_IN};
            GSeg b = {hS[wr],   fc2a_w + HQ, HS, D_FC2_IN};
            gemm_tc<<<dim3(D_FC2_H / 64, BB / 64), 128>>>(a, b, nil, 2, fc2a_b, nullptr,
                a2, D_FC2_H, 1, 0, nullptr, nullptr);
        }

        // fc2b: k_vec = a2 @ fc2b_w^T + b
        {
            GSeg a = {a2, fc2b_w, D_FC2_H, D_FC2_H};
            gemm_tc<<<dim3(NN * MM / 64, BB / 64), 128>>>(a, nil, nil, 1, fc2b_b, nullptr,
                kvec, NN * MM, 0, 0, nullptr, nullptr);
        }

        update_kernel<<<BB, 32>>>(x_prior, kvec, dy, out + (size_t)t * BB * MM);
    }
}

// round 9
// speedup vs baseline: 1.6108x; 1.0310x over previous
#include <cuda_runtime.h>
#include <cuda_bf16.h>
#include <math.h>
#include <stdint.h>

// ---------------- problem constants ----------------
#define MM   32      // state dim m
#define NN   16      // obs dim n
#define BB   256     // batch
#define TT   8       // time steps
#define HQ   1024    // m*m
#define HS   256     // n*n
#define D_Q_IN   160      // m*IN_MULT
#define D_SIG_IN 1184     // HQ + 160
#define D_S_IN   416      // 256 + 160
#define D_FC2_IN 1280     // HQ + HS
#define D_FC2_H  2560

// ---------------- device scratch (no allocations allowed) ----------------
__device__ float g_hQ  [2][BB * HQ];
__device__ float g_cQ  [BB * HQ];
__device__ float g_hSig[2][BB * HQ];
__device__ float g_cSig[BB * HQ];
__device__ float g_hS  [2][BB * HS];
__device__ float g_cS  [BB * HS];
__device__ float g_out5[BB * D_Q_IN];
__device__ float g_out6[BB * D_Q_IN];
__device__ float g_out7[BB * D_Q_IN];
__device__ float g_out1[BB * HS];
__device__ float g_a2  [BB * D_FC2_H];
__device__ float g_xprior[2][BB * MM];
__device__ float g_dy   [BB * NN];
__device__ float g_yprev0[BB * NN];

__device__ __forceinline__ float sigmoidf(float x) { return 1.f / (1.f + expf(-x)); }

// ---------------- init: zero states, y_prev0 = tanh(x0[:, :16]) ----------------
__global__ void init_kernel(const float* __restrict__ x0, float* __restrict__ yprev0)
{
    int idx = blockIdx.x * blockDim.x + threadIdx.x;
    if (idx < BB * HQ) {
        g_hQ[0][idx] = 0.f; g_hQ[1][idx] = 0.f; g_cQ[idx] = 0.f;
        g_hSig[0][idx] = 0.f; g_hSig[1][idx] = 0.f; g_cSig[idx] = 0.f;
    }
    if (idx < BB * HS) { g_hS[0][idx] = 0.f; g_hS[1][idx] = 0.f; g_cS[idx] = 0.f; }
    if (idx < BB * NN) {
        int b = idx / NN, n = idx % NN;
        yprev0[idx] = tanhf(x0[b * MM + n]);
    }
}

// ---------------- fused prologue + fc5/6/7 ----------------
__global__ void pre_fc_kernel(const float* __restrict__ x_post,
                              const float* __restrict__ x_post_prev,
                              const float* __restrict__ x_prior_prev,
                              const float* __restrict__ y_t,
                              const float* __restrict__ y_prev,
                              float* __restrict__ x_prior,
                              float* __restrict__ dy_buf,
                              const float* __restrict__ w5, const float* __restrict__ b5,
                              const float* __restrict__ w6, const float* __restrict__ b6,
                              const float* __restrict__ w7, const float* __restrict__ b7,
                              float* __restrict__ out5,
                              float* __restrict__ out6,
                              float* __restrict__ out7)
{
    int b = blockIdx.x;
    int tid = threadIdx.x;
    __shared__ float fwu[32], fwe[32], obs[32];

    if (tid < 32) {
        int lane = tid;
        float xp   = x_post[b * MM + lane];
        float xpp  = x_post_prev[b * MM + lane];
        float xprp = x_prior_prev[b * MM + lane];

        float xpr = xp + 0.1f * sinf(xp);
        x_prior[b * MM + lane] = xpr;

        float de = xp - xpp;
        float du = xp - xprp;
        float se = de * de, su = du * du;
        #pragma unroll
        for (int o = 16; o > 0; o >>= 1) {
            se += __shfl_xor_sync(0xffffffffu, se, o);
            su += __shfl_xor_sync(0xffffffffu, su, o);
        }
        fwe[lane] = de / fmaxf(sqrtf(se), 1e-12f);
        fwu[lane] = du / fmaxf(sqrtf(su), 1e-12f);

        float y     = (lane < NN) ? y_t[b * NN + lane]    : 0.f;
        float ypv   = (lane < NN) ? y_prev[b * NN + lane] : 0.f;
        float ypred = (lane < NN) ? tanhf(xpr)            : 0.f;
        float d1 = y - ypv;
        float d2 = y - ypred;
        if (lane < NN) dy_buf[b * NN + lane] = d2;
        float s1 = d1 * d1, s2 = d2 * d2;
        #pragma unroll
        for (int o = 16; o > 0; o >>= 1) {
            s1 += __shfl_xor_sync(0xffffffffu, s1, o);
            s2 += __shfl_xor_sync(0xffffffffu, s2, o);
        }
        if (lane < NN) {
            obs[lane]      = d1 / fmaxf(sqrtf(s1), 1e-12f);
            obs[NN + lane] = d2 / fmaxf(sqrtf(s2), 1e-12f);
        }
    }
    __syncthreads();

    for (int o = tid; o < 480; o += 192) {
        int which = o / 160, oo = o - which * 160;
        const float* W; const float* Bv; const float* xs; float* O;
        if (which == 0)      { W = w5; Bv = b5; xs = fwu; O = out5; }
        else if (which == 1) { W = w6; Bv = b6; xs = fwe; O = out6; }
        else                 { W = w7; Bv = b7; xs = obs; O = out7; }
        float acc = Bv[oo];
        const float* wr = W + oo * 32;
        #pragma unroll
        for (int k = 0; k < 32; k++) acc += xs[k] * wr[k];
        O[b * 160 + oo] = fmaxf(acc, 0.f);
    }
}

// ---------------- TF32 tensor-core multi-segment GEMM ----------------
// Tiles: BM=64 BN=32 BK=32, 128 threads (4 warps, 2x2), warp tile 32x16, 2-stage.
// lstmH >0          : gate-interleaved weight addressing + fused LSTM cell epilogue.
// lstmH==0, act<2   : Z = act(sum + bias0 (+bias1)).
// lstmH==0, act==2  : KF epilogue. Warp's 16-col strip == one K row m.
//                     Z[r*MM+m] = hout(x_prior)[r*MM+m] + sum_n (val+bias)*cst(dy)[r*NN+n].
struct GSeg {
    const float* X;   // [BB, K] contiguous
    const float* W;   // row-major, row stride ldw (may carry a column offset)
    int K;
    int ldw;
};

#define LDA 36   // padded smem stride for BK=32

__device__ __forceinline__ void cpa16(void* s, const void* g) {
    uint32_t sa = (uint32_t)__cvta_generic_to_shared(s);
    asm volatile("cp.async.cg.shared.global [%0], [%1], 16;\n" :: "r"(sa), "l"(g));
}
__device__ __forceinline__ uint32_t f2tf32(float f) {
    uint32_t u;
    asm("cvt.rna.tf32.f32 %0, %1;" : "=r"(u) : "f"(f));
    return u;
}

__global__ void __launch_bounds__(128) gemm_tc(
    GSeg s0, GSeg s1, GSeg s2, int nseg,
    const float* __restrict__ bias0, const float* __restrict__ bias1,
    float* __restrict__ Z, int Nout, int act,
    int lstmH, float* __restrict__ cst, float* __restrict__ hout)
{
    __shared__ float As[2][64 * LDA];
    __shared__ float Bs[2][32 * LDA];

    int tid  = threadIdx.x;
    int lane = tid & 31;
    int wid  = tid >> 5;
    int wm   = wid & 1;      // warp m (0..1) -> rows wm*32..+31
    int wn   = wid >> 1;     // warp n (0..1) -> cols wn*16..+15
    int gid  = lane >> 2;    // 0..7
    int tg   = lane & 3;     // 0..3

    int row0 = blockIdx.y * 64;
    int col0 = blockIdx.x * 32;

    // staging: A rows srow+16i (i<4), B rows srow+16i (i<2); 16B per load
    int srow = tid >> 3;          // 0..15
    int scol = (tid & 7) * 4;     // 0..28

    int brow_g[2];
    #pragma unroll
    for (int i = 0; i < 2; i++) {
        int bc = col0 + srow + 16 * i;
        brow_g[i] = lstmH ? ((bc & 3) * lstmH + (bc >> 2)) : bc;
    }

    int totK = s0.K + ((nseg > 1) ? s1.K : 0) + ((nseg > 2) ? s2.K : 0);
    int niter = totK >> 5;

    float c[2][2][4];
    #pragma unroll
    for (int mt = 0; mt < 2; mt++)
        #pragma unroll
        for (int nt = 0; nt < 2; nt++)
            #pragma unroll
            for (int r = 0; r < 4; r++) c[mt][nt][r] = 0.f;

    auto issue = [&](int it, int p) {
        int kb = it << 5;
        const float* X = s0.X; const float* W = s0.W; int K = s0.K; int ldw = s0.ldw;
        if (kb >= s0.K) {
            kb -= s0.K;
            if (nseg > 2 && kb >= s1.K) { kb -= s1.K; X = s2.X; W = s2.W; K = s2.K; ldw = s2.ldw; }
            else                        {             X = s1.X; W = s1.W; K = s1.K; ldw = s1.ldw; }
        }
        #pragma unroll
        for (int i = 0; i < 4; i++) {
            int r = srow + 16 * i;
            cpa16(&As[p][r * LDA + scol], X + (size_t)(row0 + r) * K + kb + scol);
        }
        #pragma unroll
        for (int i = 0; i < 2; i++) {
            int r = srow + 16 * i;
            cpa16(&Bs[p][r * LDA + scol], W + (size_t)brow_g[i] * ldw + kb + scol);
        }
        asm volatile("cp.async.commit_group;\n" ::);
    };

    issue(0, 0);

    for (int it = 0; it < niter; it++) {
        int p = it & 1;
        if (it + 1 < niter) {
            issue(it + 1, p ^ 1);
            asm volatile("cp.async.wait_group 1;\n" ::);
        } else {
            asm volatile("cp.async.wait_group 0;\n" ::);
        }
        __syncthreads();

        #pragma unroll
        for (int ks = 0; ks < 4; ks++) {
            int kk = ks * 8;
            uint32_t af[2][4];
            #pragma unroll
            for (int mt = 0; mt < 2; mt++) {
                int r = wm * 32 + mt * 16 + gid;
                af[mt][0] = f2tf32(As[p][r * LDA + kk + tg]);
                af[mt][1] = f2tf32(As[p][(r + 8) * LDA + kk + tg]);
                af[mt][2] = f2tf32(As[p][r * LDA + kk + tg + 4]);
                af[mt][3] = f2tf32(As[p][(r + 8) * LDA + kk + tg + 4]);
            }
            uint32_t bf[2][2];
            #pragma unroll
            for (int nt = 0; nt < 2; nt++) {
                int n = wn * 16 + nt * 8 + gid;
                bf[nt][0] = f2tf32(Bs[p][n * LDA + kk + tg]);
                bf[nt][1] = f2tf32(Bs[p][n * LDA + kk + tg + 4]);
            }
            #pragma unroll
            for (int mt = 0; mt < 2; mt++)
                #pragma unroll
                for (int nt = 0; nt < 2; nt++) {
                    asm volatile(
                        "mma.sync.aligned.m16n8k8.row.col.f32.tf32.tf32.f32 "
                        "{%0,%1,%2,%3}, {%4,%5,%6,%7}, {%8,%9}, {%0,%1,%2,%3};\n"
                        : "+f"(c[mt][nt][0]), "+f"(c[mt][nt][1]),
                          "+f"(c[mt][nt][2]), "+f"(c[mt][nt][3])
                        : "r"(af[mt][0]), "r"(af[mt][1]), "r"(af[mt][2]), "r"(af[mt][3]),
                          "r"(bf[nt][0]), "r"(bf[nt][1]));
                }
        }
        __syncthreads();
    }

    if (lstmH > 0) {
        // fused LSTM cell: lane tg even holds (i,f) of unit j, lane tg^1 holds (g,o)
        const int H = lstmH;
        #pragma unroll
        for (int mt = 0; mt < 2; mt++) {
            int r = row0 + wm * 32 + mt * 16 + gid;
            #pragma unroll
            for (int nt = 0; nt < 2; nt++) {
                int cb = col0 + wn * 16 + nt * 8 + tg * 2;   // logical col (j*4+g)
                int ro0 = (cb & 3) * H + (cb >> 2);
                int ro1 = ((cb + 1) & 3) * H + ((cb + 1) >> 2);
                float b0a = bias0[ro0] + bias1[ro0];
                float b0b = bias0[ro1] + bias1[ro1];
                float z0 = c[mt][nt][0] + b0a;
                float z1 = c[mt][nt][1] + b0b;
                float z2 = c[mt][nt][2] + b0a;
                float z3 = c[mt][nt][3] + b0b;
                float p0 = __shfl_xor_sync(0xffffffffu, z0, 1);
                float p1 = __shfl_xor_sync(0xffffffffu, z1, 1);
                float p2 = __shfl_xor_sync(0xffffffffu, z2, 1);
                float p3 = __shfl_xor_sync(0xffffffffu, z3, 1);
                if ((tg & 1) == 0) {
                    int jj = cb >> 2;
                    {
                        float si = sigmoidf(z0), sf = sigmoidf(z1);
                        float gg = tanhf(p0),    so = sigmoidf(p1);
                        float cn = sf * cst[(size_t)r * H + jj] + si * gg;
                        cst[(size_t)r * H + jj] = cn;
                        hout[(size_t)r * H + jj] = so * tanhf(cn);
                    }
                    {
                        float si = sigmoidf(z2), sf = sigmoidf(z3);
                        float gg = tanhf(p2),    so = sigmoidf(p3);
                        float cn = sf * cst[(size_t)(r + 8) * H + jj] + si * gg;
                        cst[(size_t)(r + 8) * H + jj] = cn;
                        hout[(size_t)(r + 8) * H + jj] = so * tanhf(cn);
                    }
                }
            }
        }
    } else if (act == 2) {
        // fused KF update: this warp's 16-col strip is K row m for 64 batches
        int m = (col0 >> 4) + wn;
        #pragma unroll
        for (int mt = 0; mt < 2; mt++) {
            int r = row0 + wm * 32 + mt * 16 + gid;
            float acc0 = 0.f, acc1 = 0.f;
            #pragma unroll
            for (int nt = 0; nt < 2; nt++) {
                int n = nt * 8 + tg * 2;
                int cbg = col0 + wn * 16 + n;
                float b0 = bias0[cbg], b1 = bias0[cbg + 1];
                float d0 = cst[r * NN + n],       d1 = cst[r * NN + n + 1];
                float d2 = cst[(r + 8) * NN + n], d3 = cst[(r + 8) * NN + n + 1];
                acc0 += (c[mt][nt][0] + b0) * d0 + (c[mt][nt][1] + b1) * d1;
                acc1 += (c[mt][nt][2] + b0) * d2 + (c[mt][nt][3] + b1) * d3;
            }
            acc0 += __shfl_xor_sync(0xffffffffu, acc0, 1);
            acc0 += __shfl_xor_sync(0xffffffffu, acc0, 2);
            acc1 += __shfl_xor_sync(0xffffffffu, acc1, 1);
            acc1 += __shfl_xor_sync(0xffffffffu, acc1, 2);
            if (tg == 0) {
                Z[r * MM + m]       = hout[r * MM + m]       + acc0;
                Z[(r + 8) * MM + m] = hout[(r + 8) * MM + m] + acc1;
            }
        }
    } else {
        #pragma unroll
        for (int mt = 0; mt < 2; mt++) {
            int r = row0 + wm * 32 + mt * 16 + gid;
            #pragma unroll
            for (int nt = 0; nt < 2; nt++) {
                int cb = col0 + wn * 16 + nt * 8 + tg * 2;
                float b0a = bias0[cb], b0b = bias0[cb + 1];
                if (bias1) { b0a += bias1[cb]; b0b += bias1[cb + 1]; }
                float v0 = c[mt][nt][0] + b0a;
                float v1 = c[mt][nt][1] + b0b;
                float v2 = c[mt][nt][2] + b0a;
                float v3 = c[mt][nt][3] + b0b;
                if (act) {
                    v0 = fmaxf(v0, 0.f); v1 = fmaxf(v1, 0.f);
                    v2 = fmaxf(v2, 0.f); v3 = fmaxf(v3, 0.f);
                }
                *reinterpret_cast<float2*>(&Z[(size_t)r * Nout + cb])       = make_float2(v0, v1);
                *reinterpret_cast<float2*>(&Z[(size_t)(r + 8) * Nout + cb]) = make_float2(v2, v3);
            }
        }
    }
}

// ---------------- host orchestration ----------------
extern "C" void kernel_launch(void* const* d_in, const int* in_sizes, int n_in,
                              void* d_out, int out_size)
{
    const float* Y       = (const float*)d_in[0];
    const float* x0      = (const float*)d_in[1];
    const float* Wq_ih   = (const float*)d_in[2];
    const float* Wq_hh   = (const float*)d_in[3];
    const float* bq_ih   = (const float*)d_in[4];
    const float* bq_hh   = (const float*)d_in[5];
    const float* Wsig_ih = (const float*)d_in[6];
    const float* Wsig_hh = (const float*)d_in[7];
    const float* bsig_ih = (const float*)d_in[8];
    const float* bsig_hh = (const float*)d_in[9];
    const float* Ws_ih   = (const float*)d_in[10];
    const float* Ws_hh   = (const float*)d_in[11];
    const float* bs_ih   = (const float*)d_in[12];
    const float* bs_hh   = (const float*)d_in[13];
    const float* fc1_w   = (const float*)d_in[14];
    const float* fc1_b   = (const float*)d_in[15];
    const float* fc2a_w  = (const float*)d_in[16];
    const float* fc2a_b  = (const float*)d_in[17];
    const float* fc2b_w  = (const float*)d_in[18];
    const float* fc2b_b  = (const float*)d_in[19];
    const float* fc5_w   = (const float*)d_in[20];
    const float* fc5_b   = (const float*)d_in[21];
    const float* fc6_w   = (const float*)d_in[22];
    const float* fc6_b   = (const float*)d_in[23];
    const float* fc7_w   = (const float*)d_in[24];
    const float* fc7_b   = (const float*)d_in[25];

    float* out = (float*)d_out;   // [T, B, M, 1]

    float *hQ0, *cQ, *hSig0, *cSig, *hS0, *cS;
    float *out5, *out6, *out7, *out1, *a2;
    float *xprior0, *dy, *yprev0;
    cudaGetSymbolAddress((void**)&hQ0,   g_hQ);
    cudaGetSymbolAddress((void**)&cQ,    g_cQ);
    cudaGetSymbolAddress((void**)&hSig0, g_hSig);
    cudaGetSymbolAddress((void**)&cSig,  g_cSig);
    cudaGetSymbolAddress((void**)&hS0,   g_hS);
    cudaGetSymbolAddress((void**)&cS,    g_cS);
    cudaGetSymbolAddress((void**)&out5,  g_out5);
    cudaGetSymbolAddress((void**)&out6,  g_out6);
    cudaGetSymbolAddress((void**)&out7,  g_out7);
    cudaGetSymbolAddress((void**)&out1,  g_out1);
    cudaGetSymbolAddress((void**)&a2,    g_a2);
    cudaGetSymbolAddress((void**)&xprior0, g_xprior);
    cudaGetSymbolAddress((void**)&dy,    g_dy);
    cudaGetSymbolAddress((void**)&yprev0,g_yprev0);

    float* hQ[2]   = {hQ0,   hQ0   + BB * HQ};
    float* hSig[2] = {hSig0, hSig0 + BB * HQ};
    float* hS[2]   = {hS0,   hS0   + BB * HS};
    float* xprior_buf[2] = {xprior0, xprior0 + BB * MM};

    const GSeg nil = {nullptr, nullptr, 0, 0};

    init_kernel<<<(BB * HQ + 255) / 256, 256>>>(x0, yprev0);

    for (int t = 0; t < TT; t++) {
        const float* x_post      = (t == 0) ? x0 : out + (size_t)(t - 1) * BB * MM;
        const float* x_post_prev = (t <= 1) ? x0 : out + (size_t)(t - 2) * BB * MM;
        const float* x_prior_prev= (t == 0) ? x0 : xprior_buf[(t - 1) & 1];
        const float* y_t         = Y + (size_t)t * BB * NN;
        const float* y_prev      = (t == 0) ? yprev0 : Y + (size_t)(t - 1) * BB * NN;
        float* x_prior           = xprior_buf[t & 1];
        int rd = t & 1, wr = rd ^ 1;

        pre_fc_kernel<<<BB, 192>>>(x_post, x_post_prev, x_prior_prev, y_t, y_prev,
                                   x_prior, dy,
                                   fc5_w, fc5_b, fc6_w, fc6_b, fc7_w, fc7_b,
                                   out5, out6, out7);

        // LSTM Q (fused cell epilogue, gate-interleaved addressing on original weights)
        {
            GSeg a = {out5,   Wq_ih, D_Q_IN, D_Q_IN};
            GSeg b = {hQ[rd], Wq_hh, HQ,     HQ};
            gemm_tc<<<dim3(4 * HQ / 32, BB / 64), 128>>>(a, b, nil, 2, bq_ih, bq_hh,
                nullptr, 0, 0, HQ, cQ, hQ[wr]);
        }

        // LSTM Sigma: input = concat(hQ_new, out6)
        {
            GSeg a = {hQ[wr],   Wsig_ih,        HQ,     D_SIG_IN};
            GSeg b = {out6,     Wsig_ih + HQ,   D_Q_IN, D_SIG_IN};
            GSeg c = {hSig[rd], Wsig_hh,        HQ,     HQ};
            gemm_tc<<<dim3(4 * HQ / 32, BB / 64), 128>>>(a, b, c, 3, bsig_ih, bsig_hh,
                nullptr, 0, 0, HQ, cSig, hSig[wr]);
        }

        // fc1: relu(hSig_new @ fc1_w^T + b)
        {
            GSeg a = {hSig[wr], fc1_w, HQ, HQ};
            gemm_tc<<<dim3(HS / 32, BB / 64), 128>>>(a, nil, nil, 1, fc1_b, nullptr,
                out1, HS, 1, 0, nullptr, nullptr);
        }

        // LSTM S: input = concat(out1, out7)
        {
            GSeg a = {out1,   Ws_ih,       HS,     D_S_IN};
            GSeg b = {out7,   Ws_ih + HS,  D_Q_IN, D_S_IN};
            GSeg c = {hS[rd], Ws_hh,       HS,     HS};
            gemm_tc<<<dim3(4 * HS / 32, BB / 64), 128>>>(a, b, c, 3, bs_ih, bs_hh,
                nullptr, 0, 0, HS, cS, hS[wr]);
        }

        // fc2a: relu(concat(hSig_new, hS_new) @ fc2a_w^T + b)
        {
            GSeg a = {hSig[wr], fc2a_w,      HQ, D_FC2_IN};
            GSeg b = {hS[wr],   fc2a_w + HQ, HS, D_FC2_IN};
            gemm_tc<<<dim3(D_FC2_H / 32, BB / 64), 128>>>(a, b, nil, 2, fc2a_b, nullptr,
                a2, D_FC2_H, 1, 0, nullptr, nullptr);
        }

        // fc2b + fused KF update: out[t] = x_prior + (a2 @ fc2b_w^T + b) @ dy
        {
            GSeg a = {a2, fc2b_w, D_FC2_H, D_FC2_H};
            gemm_tc<<<dim3(NN * MM / 32, BB / 64), 128>>>(a, nil, nil, 1, fc2b_b, nullptr,
                out + (size_t)t * BB * MM, MM, 2, 0, dy, x_prior);
        }
    }
}

// round 10
// speedup vs baseline: 1.8480x; 1.1473x over previous
#include <cuda_runtime.h>
#include <cuda_bf16.h>
#include <cuda_fp16.h>
#include <math.h>
#include <stdint.h>

// ---------------- problem constants ----------------
#define MM   32      // state dim m
#define NN   16      // obs dim n
#define BB   256     // batch
#define TT   8       // time steps
#define HQ   1024    // m*m
#define HS   256     // n*n
#define D_Q_IN   160      // m*IN_MULT
#define D_SIG_IN 1184     // HQ + 160
#define D_S_IN   416      // 256 + 160
#define D_FC2_IN 1280     // HQ + HS
#define D_FC2_H  2560

// ---------------- device scratch (no allocations allowed) ----------------
__device__ float g_hQ  [2][BB * HQ];
__device__ float g_cQ  [BB * HQ];
__device__ float g_hSig[2][BB * HQ];
__device__ float g_cSig[BB * HQ];
__device__ float g_hS  [2][BB * HS];
__device__ float g_cS  [BB * HS];
__device__ float g_out5[BB * D_Q_IN];
__device__ float g_out6[BB * D_Q_IN];
__device__ float g_out7[BB * D_Q_IN];
__device__ float g_out1[BB * HS];
__device__ float g_a2  [BB * D_FC2_H];
__device__ float g_xprior[2][BB * MM];
__device__ float g_dy   [BB * NN];
__device__ float g_yprev0[BB * NN];

__device__ __forceinline__ float sigmoidf(float x) { return 1.f / (1.f + expf(-x)); }

// ---------------- init: zero states, y_prev0 = tanh(x0[:, :16]) ----------------
__global__ void init_kernel(const float* __restrict__ x0, float* __restrict__ yprev0)
{
    int idx = blockIdx.x * blockDim.x + threadIdx.x;
    if (idx < BB * HQ) {
        g_hQ[0][idx] = 0.f; g_hQ[1][idx] = 0.f; g_cQ[idx] = 0.f;
        g_hSig[0][idx] = 0.f; g_hSig[1][idx] = 0.f; g_cSig[idx] = 0.f;
    }
    if (idx < BB * HS) { g_hS[0][idx] = 0.f; g_hS[1][idx] = 0.f; g_cS[idx] = 0.f; }
    if (idx < BB * NN) {
        int b = idx / NN, n = idx % NN;
        yprev0[idx] = tanhf(x0[b * MM + n]);
    }
}

// ---------------- fused prologue + fc5/6/7 ----------------
__global__ void pre_fc_kernel(const float* __restrict__ x_post,
                              const float* __restrict__ x_post_prev,
                              const float* __restrict__ x_prior_prev,
                              const float* __restrict__ y_t,
                              const float* __restrict__ y_prev,
                              float* __restrict__ x_prior,
                              float* __restrict__ dy_buf,
                              const float* __restrict__ w5, const float* __restrict__ b5,
                              const float* __restrict__ w6, const float* __restrict__ b6,
                              const float* __restrict__ w7, const float* __restrict__ b7,
                              float* __restrict__ out5,
                              float* __restrict__ out6,
                              float* __restrict__ out7)
{
    int b = blockIdx.x;
    int tid = threadIdx.x;
    __shared__ float fwu[32], fwe[32], obs[32];

    if (tid < 32) {
        int lane = tid;
        float xp   = x_post[b * MM + lane];
        float xpp  = x_post_prev[b * MM + lane];
        float xprp = x_prior_prev[b * MM + lane];

        float xpr = xp + 0.1f * sinf(xp);
        x_prior[b * MM + lane] = xpr;

        float de = xp - xpp;
        float du = xp - xprp;
        float se = de * de, su = du * du;
        #pragma unroll
        for (int o = 16; o > 0; o >>= 1) {
            se += __shfl_xor_sync(0xffffffffu, se, o);
            su += __shfl_xor_sync(0xffffffffu, su, o);
        }
        fwe[lane] = de / fmaxf(sqrtf(se), 1e-12f);
        fwu[lane] = du / fmaxf(sqrtf(su), 1e-12f);

        float y     = (lane < NN) ? y_t[b * NN + lane]    : 0.f;
        float ypv   = (lane < NN) ? y_prev[b * NN + lane] : 0.f;
        float ypred = (lane < NN) ? tanhf(xpr)            : 0.f;
        float d1 = y - ypv;
        float d2 = y - ypred;
        if (lane < NN) dy_buf[b * NN + lane] = d2;
        float s1 = d1 * d1, s2 = d2 * d2;
        #pragma unroll
        for (int o = 16; o > 0; o >>= 1) {
            s1 += __shfl_xor_sync(0xffffffffu, s1, o);
            s2 += __shfl_xor_sync(0xffffffffu, s2, o);
        }
        if (lane < NN) {
            obs[lane]      = d1 / fmaxf(sqrtf(s1), 1e-12f);
            obs[NN + lane] = d2 / fmaxf(sqrtf(s2), 1e-12f);
        }
    }
    __syncthreads();

    for (int o = tid; o < 480; o += 192) {
        int which = o / 160, oo = o - which * 160;
        const float* W; const float* Bv; const float* xs; float* O;
        if (which == 0)      { W = w5; Bv = b5; xs = fwu; O = out5; }
        else if (which == 1) { W = w6; Bv = b6; xs = fwe; O = out6; }
        else                 { W = w7; Bv = b7; xs = obs; O = out7; }
        float acc = Bv[oo];
        const float* wr = W + oo * 32;
        #pragma unroll
        for (int k = 0; k < 32; k++) acc += xs[k] * wr[k];
        O[b * 160 + oo] = fmaxf(acc, 0.f);
    }
}

// ---------------- FP16 tensor-core multi-segment GEMM (fp32 accumulate) ----------------
// Tiles: BM=64 BN=64 BK=32, 128 threads (4 warps 2x2), warp tile 32x32, 2-stage cp.async.
// Fragments converted f32->f16x2 at load (11-bit significand == tf32 precision).
// lstmH >0          : gate-interleaved weight addressing + fused LSTM cell epilogue.
// lstmH==0, act<2   : Z = act(sum + bias0 (+bias1)).
// lstmH==0, act==2  : KF epilogue; warp's 32-col strip = 2 K rows m.
struct GSeg {
    const float* X;   // [BB, K] contiguous
    const float* W;   // row-major, row stride ldw (may carry a column offset)
    int K;
    int ldw;
};

#define LDA 40   // padded smem stride (floats): gid-stride 40 ≡ 8 (mod 32) -> conflict-free float2 loads

__device__ __forceinline__ void cpa16(void* s, const void* g) {
    uint32_t sa = (uint32_t)__cvta_generic_to_shared(s);
    asm volatile("cp.async.cg.shared.global [%0], [%1], 16;\n" :: "r"(sa), "l"(g));
}
// pack two f32 into f16x2: lo -> low half, hi -> high half
__device__ __forceinline__ uint32_t pack_h2(float lo, float hi) {
    uint32_t u;
    asm("cvt.rn.f16x2.f32 %0, %1, %2;" : "=r"(u) : "f"(hi), "f"(lo));
    return u;
}

__global__ void __launch_bounds__(128) gemm_tc(
    GSeg s0, GSeg s1, GSeg s2, int nseg,
    const float* __restrict__ bias0, const float* __restrict__ bias1,
    float* __restrict__ Z, int Nout, int act,
    int lstmH, float* __restrict__ cst, float* __restrict__ hout)
{
    __shared__ float As[2][64 * LDA];
    __shared__ float Bs[2][64 * LDA];

    int tid  = threadIdx.x;
    int lane = tid & 31;
    int wid  = tid >> 5;
    int wm   = wid & 1;      // warp m (0..1) -> rows wm*32..+31
    int wn   = wid >> 1;     // warp n (0..1) -> cols wn*32..+31
    int gid  = lane >> 2;    // 0..7
    int tg   = lane & 3;     // 0..3

    int row0 = blockIdx.y * 64;
    int col0 = blockIdx.x * 64;

    // staging: rows srow+16i (i<4) for both A and B; 16B per load
    int srow = tid >> 3;          // 0..15
    int scol = (tid & 7) * 4;     // 0..28

    int brow_g[4];
    #pragma unroll
    for (int i = 0; i < 4; i++) {
        int bc = col0 + srow + 16 * i;
        brow_g[i] = lstmH ? ((bc & 3) * lstmH + (bc >> 2)) : bc;
    }

    int totK = s0.K + ((nseg > 1) ? s1.K : 0) + ((nseg > 2) ? s2.K : 0);
    int niter = totK >> 5;

    float c[2][4][4];
    #pragma unroll
    for (int mt = 0; mt < 2; mt++)
        #pragma unroll
        for (int nt = 0; nt < 4; nt++)
            #pragma unroll
            for (int r = 0; r < 4; r++) c[mt][nt][r] = 0.f;

    auto issue = [&](int it, int p) {
        int kb = it << 5;
        const float* X = s0.X; const float* W = s0.W; int K = s0.K; int ldw = s0.ldw;
        if (kb >= s0.K) {
            kb -= s0.K;
            if (nseg > 2 && kb >= s1.K) { kb -= s1.K; X = s2.X; W = s2.W; K = s2.K; ldw = s2.ldw; }
            else                        {             X = s1.X; W = s1.W; K = s1.K; ldw = s1.ldw; }
        }
        #pragma unroll
        for (int i = 0; i < 4; i++) {
            int r = srow + 16 * i;
            cpa16(&As[p][r * LDA + scol], X + (size_t)(row0 + r) * K + kb + scol);
            cpa16(&Bs[p][r * LDA + scol], W + (size_t)brow_g[i] * ldw + kb + scol);
        }
        asm volatile("cp.async.commit_group;\n" ::);
    };

    issue(0, 0);

    for (int it = 0; it < niter; it++) {
        int p = it & 1;
        if (it + 1 < niter) {
            issue(it + 1, p ^ 1);
            asm volatile("cp.async.wait_group 1;\n" ::);
        } else {
            asm volatile("cp.async.wait_group 0;\n" ::);
        }
        __syncthreads();

        #pragma unroll
        for (int ks = 0; ks < 2; ks++) {
            int kk = ks * 16;
            // A fragments: 2 m-tiles x 4 regs (m16n8k16 layout)
            uint32_t af[2][4];
            #pragma unroll
            for (int mt = 0; mt < 2; mt++) {
                int r = wm * 32 + mt * 16 + gid;
                float2 v0 = *reinterpret_cast<const float2*>(&As[p][r * LDA + kk + tg * 2]);
                float2 v1 = *reinterpret_cast<const float2*>(&As[p][(r + 8) * LDA + kk + tg * 2]);
                float2 v2 = *reinterpret_cast<const float2*>(&As[p][r * LDA + kk + 8 + tg * 2]);
                float2 v3 = *reinterpret_cast<const float2*>(&As[p][(r + 8) * LDA + kk + 8 + tg * 2]);
                af[mt][0] = pack_h2(v0.x, v0.y);
                af[mt][1] = pack_h2(v1.x, v1.y);
                af[mt][2] = pack_h2(v2.x, v2.y);
                af[mt][3] = pack_h2(v3.x, v3.y);
            }
            // B fragments: 4 n-tiles x 2 regs
            uint32_t bf[4][2];
            #pragma unroll
            for (int nt = 0; nt < 4; nt++) {
                int n = wn * 32 + nt * 8 + gid;
                float2 w0 = *reinterpret_cast<const float2*>(&Bs[p][n * LDA + kk + tg * 2]);
                float2 w1 = *reinterpret_cast<const float2*>(&Bs[p][n * LDA + kk + 8 + tg * 2]);
                bf[nt][0] = pack_h2(w0.x, w0.y);
                bf[nt][1] = pack_h2(w1.x, w1.y);
            }
            #pragma unroll
            for (int mt = 0; mt < 2; mt++)
                #pragma unroll
                for (int nt = 0; nt < 4; nt++) {
                    asm volatile(
                        "mma.sync.aligned.m16n8k16.row.col.f32.f16.f16.f32 "
                        "{%0,%1,%2,%3}, {%4,%5,%6,%7}, {%8,%9}, {%0,%1,%2,%3};\n"
                        : "+f"(c[mt][nt][0]), "+f"(c[mt][nt][1]),
                          "+f"(c[mt][nt][2]), "+f"(c[mt][nt][3])
                        : "r"(af[mt][0]), "r"(af[mt][1]), "r"(af[mt][2]), "r"(af[mt][3]),
                          "r"(bf[nt][0]), "r"(bf[nt][1]));
                }
        }
        __syncthreads();
    }

    if (lstmH > 0) {
        // fused LSTM cell: lane tg even holds (i,f) of unit j, lane tg^1 holds (g,o)
        const int H = lstmH;
        #pragma unroll
        for (int mt = 0; mt < 2; mt++) {
            int r = row0 + wm * 32 + mt * 16 + gid;
            #pragma unroll
            for (int nt = 0; nt < 4; nt++) {
                int cb = col0 + wn * 32 + nt * 8 + tg * 2;   // logical col (j*4+g)
                int ro0 = (cb & 3) * H + (cb >> 2);
                int ro1 = ((cb + 1) & 3) * H + ((cb + 1) >> 2);
                float b0a = bias0[ro0] + bias1[ro0];
                float b0b = bias0[ro1] + bias1[ro1];
                float z0 = c[mt][nt][0] + b0a;
                float z1 = c[mt][nt][1] + b0b;
                float z2 = c[mt][nt][2] + b0a;
                float z3 = c[mt][nt][3] + b0b;
                float p0 = __shfl_xor_sync(0xffffffffu, z0, 1);
                float p1 = __shfl_xor_sync(0xffffffffu, z1, 1);
                float p2 = __shfl_xor_sync(0xffffffffu, z2, 1);
                float p3 = __shfl_xor_sync(0xffffffffu, z3, 1);
                if ((tg & 1) == 0) {
                    int jj = cb >> 2;
                    {
                        float si = sigmoidf(z0), sf = sigmoidf(z1);
                        float gg = tanhf(p0),    so = sigmoidf(p1);
                        float cn = sf * cst[(size_t)r * H + jj] + si * gg;
                        cst[(size_t)r * H + jj] = cn;
                        hout[(size_t)r * H + jj] = so * tanhf(cn);
                    }
                    {
                        float si = sigmoidf(z2), sf = sigmoidf(z3);
                        float gg = tanhf(p2),    so = sigmoidf(p3);
                        float cn = sf * cst[(size_t)(r + 8) * H + jj] + si * gg;
                        cst[(size_t)(r + 8) * H + jj] = cn;
                        hout[(size_t)(r + 8) * H + jj] = so * tanhf(cn);
                    }
                }
            }
        }
    } else if (act == 2) {
        // fused KF update: warp's 32-col strip = K rows mbase, mbase+1 (16 cols each)
        int mbase = (col0 >> 4) + wn * 2;
        #pragma unroll
        for (int mt = 0; mt < 2; mt++) {
            int r = row0 + wm * 32 + mt * 16 + gid;
            float accA0 = 0.f, accA1 = 0.f;   // m = mbase   (nt 0,1)
            float accB0 = 0.f, accB1 = 0.f;   // m = mbase+1 (nt 2,3)
            #pragma unroll
            for (int nt = 0; nt < 4; nt++) {
                int n = (nt & 1) * 8 + tg * 2;            // col within the 16-strip
                int cbg = col0 + wn * 32 + nt * 8 + tg * 2;
                float b0 = bias0[cbg], b1 = bias0[cbg + 1];
                float d0 = cst[r * NN + n],       d1 = cst[r * NN + n + 1];
                float d2 = cst[(r + 8) * NN + n], d3 = cst[(r + 8) * NN + n + 1];
                float t0 = (c[mt][nt][0] + b0) * d0 + (c[mt][nt][1] + b1) * d1;
                float t1 = (c[mt][nt][2] + b0) * d2 + (c[mt][nt][3] + b1) * d3;
                if (nt < 2) { accA0 += t0; accA1 += t1; }
                else        { accB0 += t0; accB1 += t1; }
            }
            accA0 += __shfl_xor_sync(0xffffffffu, accA0, 1);
            accA0 += __shfl_xor_sync(0xffffffffu, accA0, 2);
            accA1 += __shfl_xor_sync(0xffffffffu, accA1, 1);
            accA1 += __shfl_xor_sync(0xffffffffu, accA1, 2);
            accB0 += __shfl_xor_sync(0xffffffffu, accB0, 1);
            accB0 += __shfl_xor_sync(0xffffffffu, accB0, 2);
            accB1 += __shfl_xor_sync(0xffffffffu, accB1, 1);
            accB1 += __shfl_xor_sync(0xffffffffu, accB1, 2);
            if (tg == 0) {
                int m0 = mbase, m1 = mbase + 1;
                Z[r * MM + m0]       = hout[r * MM + m0]       + accA0;
                Z[(r + 8) * MM + m0] = hout[(r + 8) * MM + m0] + accA1;
                Z[r * MM + m1]       = hout[r * MM + m1]       + accB0;
                Z[(r + 8) * MM + m1] = hout[(r + 8) * MM + m1] + accB1;
            }
        }
    } else {
        #pragma unroll
        for (int mt = 0; mt < 2; mt++) {
            int r = row0 + wm * 32 + mt * 16 + gid;
            #pragma unroll
            for (int nt = 0; nt < 4; nt++) {
                int cb = col0 + wn * 32 + nt * 8 + tg * 2;
                float b0a = bias0[cb], b0b = bias0[cb + 1];
                if (bias1) { b0a += bias1[cb]; b0b += bias1[cb + 1]; }
                float v0 = c[mt][nt][0] + b0a;
                float v1 = c[mt][nt][1] + b0b;
                float v2 = c[mt][nt][2] + b0a;
                float v3 = c[mt][nt][3] + b0b;
                if (act) {
                    v0 = fmaxf(v0, 0.f); v1 = fmaxf(v1, 0.f);
                    v2 = fmaxf(v2, 0.f); v3 = fmaxf(v3, 0.f);
                }
                *reinterpret_cast<float2*>(&Z[(size_t)r * Nout + cb])       = make_float2(v0, v1);
                *reinterpret_cast<float2*>(&Z[(size_t)(r + 8) * Nout + cb]) = make_float2(v2, v3);
            }
        }
    }
}

// ---------------- host orchestration ----------------
extern "C" void kernel_launch(void* const* d_in, const int* in_sizes, int n_in,
                              void* d_out, int out_size)
{
    const float* Y       = (const float*)d_in[0];
    const float* x0      = (const float*)d_in[1];
    const float* Wq_ih   = (const float*)d_in[2];
    const float* Wq_hh   = (const float*)d_in[3];
    const float* bq_ih   = (const float*)d_in[4];
    const float* bq_hh   = (const float*)d_in[5];
    const float* Wsig_ih = (const float*)d_in[6];
    const float* Wsig_hh = (const float*)d_in[7];
    const float* bsig_ih = (const float*)d_in[8];
    const float* bsig_hh = (const float*)d_in[9];
    const float* Ws_ih   = (const float*)d_in[10];
    const float* Ws_hh   = (const float*)d_in[11];
    const float* bs_ih   = (const float*)d_in[12];
    const float* bs_hh   = (const float*)d_in[13];
    const float* fc1_w   = (const float*)d_in[14];
    const float* fc1_b   = (const float*)d_in[15];
    const float* fc2a_w  = (const float*)d_in[16];
    const float* fc2a_b  = (const float*)d_in[17];
    const float* fc2b_w  = (const float*)d_in[18];
    const float* fc2b_b  = (const float*)d_in[19];
    const float* fc5_w   = (const float*)d_in[20];
    const float* fc5_b   = (const float*)d_in[21];
    const float* fc6_w   = (const float*)d_in[22];
    const float* fc6_b   = (const float*)d_in[23];
    const float* fc7_w   = (const float*)d_in[24];
    const float* fc7_b   = (const float*)d_in[25];

    float* out = (float*)d_out;   // [T, B, M, 1]

    float *hQ0, *cQ, *hSig0, *cSig, *hS0, *cS;
    float *out5, *out6, *out7, *out1, *a2;
    float *xprior0, *dy, *yprev0;
    cudaGetSymbolAddress((void**)&hQ0,   g_hQ);
    cudaGetSymbolAddress((void**)&cQ,    g_cQ);
    cudaGetSymbolAddress((void**)&hSig0, g_hSig);
    cudaGetSymbolAddress((void**)&cSig,  g_cSig);
    cudaGetSymbolAddress((void**)&hS0,   g_hS);
    cudaGetSymbolAddress((void**)&cS,    g_cS);
    cudaGetSymbolAddress((void**)&out5,  g_out5);
    cudaGetSymbolAddress((void**)&out6,  g_out6);
    cudaGetSymbolAddress((void**)&out7,  g_out7);
    cudaGetSymbolAddress((void**)&out1,  g_out1);
    cudaGetSymbolAddress((void**)&a2,    g_a2);
    cudaGetSymbolAddress((void**)&xprior0, g_xprior);
    cudaGetSymbolAddress((void**)&dy,    g_dy);
    cudaGetSymbolAddress((void**)&yprev0,g_yprev0);

    float* hQ[2]   = {hQ0,   hQ0   + BB * HQ};
    float* hSig[2] = {hSig0, hSig0 + BB * HQ};
    float* hS[2]   = {hS0,   hS0   + BB * HS};
    float* xprior_buf[2] = {xprior0, xprior0 + BB * MM};

    const GSeg nil = {nullptr, nullptr, 0, 0};

    init_kernel<<<(BB * HQ + 255) / 256, 256>>>(x0, yprev0);

    for (int t = 0; t < TT; t++) {
        const float* x_post      = (t == 0) ? x0 : out + (size_t)(t - 1) * BB * MM;
        const float* x_post_prev = (t <= 1) ? x0 : out + (size_t)(t - 2) * BB * MM;
        const float* x_prior_prev= (t == 0) ? x0 : xprior_buf[(t - 1) & 1];
        const float* y_t         = Y + (size_t)t * BB * NN;
        const float* y_prev      = (t == 0) ? yprev0 : Y + (size_t)(t - 1) * BB * NN;
        float* x_prior           = xprior_buf[t & 1];
        int rd = t & 1, wr = rd ^ 1;

        pre_fc_kernel<<<BB, 192>>>(x_post, x_post_prev, x_prior_prev, y_t, y_prev,
                                   x_prior, dy,
                                   fc5_w, fc5_b, fc6_w, fc6_b, fc7_w, fc7_b,
                                   out5, out6, out7);

        // LSTM Q (fused cell epilogue, gate-interleaved addressing on original weights)
        {
            GSeg a = {out5,   Wq_ih, D_Q_IN, D_Q_IN};
            GSeg b = {hQ[rd], Wq_hh, HQ,     HQ};
            gemm_tc<<<dim3(4 * HQ / 64, BB / 64), 128>>>(a, b, nil, 2, bq_ih, bq_hh,
                nullptr, 0, 0, HQ, cQ, hQ[wr]);
        }

        // LSTM Sigma: input = concat(hQ_new, out6)
        {
            GSeg a = {hQ[wr],   Wsig_ih,        HQ,     D_SIG_IN};
            GSeg b = {out6,     Wsig_ih + HQ,   D_Q_IN, D_SIG_IN};
            GSeg c = {hSig[rd], Wsig_hh,        HQ,     HQ};
            gemm_tc<<<dim3(4 * HQ / 64, BB / 64), 128>>>(a, b, c, 3, bsig_ih, bsig_hh,
                nullptr, 0, 0, HQ, cSig, hSig[wr]);
        }

        // fc1: relu(hSig_new @ fc1_w^T + b)
        {
            GSeg a = {hSig[wr], fc1_w, HQ, HQ};
            gemm_tc<<<dim3(HS / 64, BB / 64), 128>>>(a, nil, nil, 1, fc1_b, nullptr,
                out1, HS, 1, 0, nullptr, nullptr);
        }

        // LSTM S: input = concat(out1, out7)
        {
            GSeg a = {out1,   Ws_ih,       HS,     D_S_IN};
            GSeg b = {out7,   Ws_ih + HS,  D_Q_IN, D_S_IN};
            GSeg c = {hS[rd], Ws_hh,       HS,     HS};
            gemm_tc<<<dim3(4 * HS / 64, BB / 64), 128>>>(a, b, c, 3, bs_ih, bs_hh,
                nullptr, 0, 0, HS, cS, hS[wr]);
        }

        // fc2a: relu(concat(hSig_new, hS_new) @ fc2a_w^T + b)
        {
            GSeg a = {hSig[wr], fc2a_w,      HQ, D_FC2_IN};
            GSeg b = {hS[wr],   fc2a_w + HQ, HS, D_FC2_IN};
            gemm_tc<<<dim3(D_FC2_H / 64, BB / 64), 128>>>(a, b, nil, 2, fc2a_b, nullptr,
                a2, D_FC2_H, 1, 0, nullptr, nullptr);
        }

        // fc2b + fused KF update: out[t] = x_prior + (a2 @ fc2b_w^T + b) @ dy
        {
            GSeg a = {a2, fc2b_w, D_FC2_H, D_FC2_H};
            gemm_tc<<<dim3(NN * MM / 64, BB / 64), 128>>>(a, nil, nil, 1, fc2b_b, nullptr,
                out + (size_t)t * BB * MM, MM, 2, 0, dy, x_prior);
        }
    }
}

// round 11
// speedup vs baseline: 2.2377x; 1.2109x over previous
#include <cuda_runtime.h>
#include <cuda_bf16.h>
#include <cuda_fp16.h>
#include <math.h>
#include <stdint.h>

// ---------------- problem constants ----------------
#define MM   32
#define NN   16
#define BB   256
#define TT   8
#define HQ   1024
#define HS   256
#define D_Q_IN   160
#define D_SIG_IN 1184
#define D_S_IN   416
#define D_FC2_IN 1280
#define D_FC2_H  2560

// ---------------- device scratch ----------------
// fp16 weights (LSTM ones gate-interleaved: dst row j*4+g <- src row g*H+j)
__device__ __half g_WqihH [4 * HQ * D_Q_IN];
__device__ __half g_WqhhH [4 * HQ * HQ];
__device__ __half g_WsigihH[4 * HQ * D_SIG_IN];
__device__ __half g_WsighhH[4 * HQ * HQ];
__device__ __half g_WsihH [4 * HS * D_S_IN];
__device__ __half g_WshhH [4 * HS * HS];
__device__ __half g_fc1H  [HS * HQ];
__device__ __half g_fc2aH [D_FC2_H * D_FC2_IN];
__device__ __half g_fc2bH [NN * MM * D_FC2_H];
// fp16 activations
__device__ __half g_hQh  [2][BB * HQ];
__device__ __half g_hSigh[2][BB * HQ];
__device__ __half g_hSh  [2][BB * HS];
__device__ __half g_out5h[BB * D_Q_IN];
__device__ __half g_out6h[BB * D_Q_IN];
__device__ __half g_out7h[BB * D_Q_IN];
__device__ __half g_out1h[BB * HS];
__device__ __half g_a2h  [BB * D_FC2_H];
// fp32 state
__device__ float g_cQ  [BB * HQ];
__device__ float g_cSig[BB * HQ];
__device__ float g_cS  [BB * HS];
__device__ float g_xprior[2][BB * MM];
__device__ float g_dy   [BB * NN];
__device__ float g_yprev0[BB * NN];

__device__ __forceinline__ float sigmoidf(float x) { return 1.f / (1.f + expf(-x)); }

// ---------------- weight f32->f16 (+optional gate interleave) ----------------
__global__ void cvt_w(const float* __restrict__ src, __half* __restrict__ dst,
                      int K, int H)   // grid.x = dst rows; H=0 -> identity row map
{
    int rp = blockIdx.x;
    int ro = H ? ((rp & 3) * H + (rp >> 2)) : rp;
    const float2* s = (const float2*)(src + (size_t)ro * K);
    __half2* d = (__half2*)(dst + (size_t)rp * K);
    for (int k = threadIdx.x; k < (K >> 1); k += blockDim.x) {
        float2 v = s[k];
        d[k] = __floats2half2_rn(v.x, v.y);
    }
}

// ---------------- init: zero states, y_prev0 = tanh(x0[:, :16]) ----------------
__global__ void init_kernel(const float* __restrict__ x0, float* __restrict__ yprev0)
{
    int idx = blockIdx.x * blockDim.x + threadIdx.x;
    __half hz = __float2half(0.f);
    if (idx < BB * HQ) {
        g_hQh[0][idx] = hz; g_hQh[1][idx] = hz; g_cQ[idx] = 0.f;
        g_hSigh[0][idx] = hz; g_hSigh[1][idx] = hz; g_cSig[idx] = 0.f;
    }
    if (idx < BB * HS) { g_hSh[0][idx] = hz; g_hSh[1][idx] = hz; g_cS[idx] = 0.f; }
    if (idx < BB * NN) {
        int b = idx / NN, n = idx % NN;
        yprev0[idx] = tanhf(x0[b * MM + n]);
    }
}

// ---------------- fused prologue + fc5/6/7 (fp16 outputs) ----------------
__global__ void pre_fc_kernel(const float* __restrict__ x_post,
                              const float* __restrict__ x_post_prev,
                              const float* __restrict__ x_prior_prev,
                              const float* __restrict__ y_t,
                              const float* __restrict__ y_prev,
                              float* __restrict__ x_prior,
                              float* __restrict__ dy_buf,
                              const float* __restrict__ w5, const float* __restrict__ b5,
                              const float* __restrict__ w6, const float* __restrict__ b6,
                              const float* __restrict__ w7, const float* __restrict__ b7,
                              __half* __restrict__ out5,
                              __half* __restrict__ out6,
                              __half* __restrict__ out7)
{
    int b = blockIdx.x;
    int tid = threadIdx.x;
    __shared__ float fwu[32], fwe[32], obs[32];

    if (tid < 32) {
        int lane = tid;
        float xp   = x_post[b * MM + lane];
        float xpp  = x_post_prev[b * MM + lane];
        float xprp = x_prior_prev[b * MM + lane];

        float xpr = xp + 0.1f * sinf(xp);
        x_prior[b * MM + lane] = xpr;

        float de = xp - xpp;
        float du = xp - xprp;
        float se = de * de, su = du * du;
        #pragma unroll
        for (int o = 16; o > 0; o >>= 1) {
            se += __shfl_xor_sync(0xffffffffu, se, o);
            su += __shfl_xor_sync(0xffffffffu, su, o);
        }
        fwe[lane] = de / fmaxf(sqrtf(se), 1e-12f);
        fwu[lane] = du / fmaxf(sqrtf(su), 1e-12f);

        float y     = (lane < NN) ? y_t[b * NN + lane]    : 0.f;
        float ypv   = (lane < NN) ? y_prev[b * NN + lane] : 0.f;
        float ypred = (lane < NN) ? tanhf(xpr)            : 0.f;
        float d1 = y - ypv;
        float d2 = y - ypred;
        if (lane < NN) dy_buf[b * NN + lane] = d2;
        float s1 = d1 * d1, s2 = d2 * d2;
        #pragma unroll
        for (int o = 16; o > 0; o >>= 1) {
            s1 += __shfl_xor_sync(0xffffffffu, s1, o);
            s2 += __shfl_xor_sync(0xffffffffu, s2, o);
        }
        if (lane < NN) {
            obs[lane]      = d1 / fmaxf(sqrtf(s1), 1e-12f);
            obs[NN + lane] = d2 / fmaxf(sqrtf(s2), 1e-12f);
        }
    }
    __syncthreads();

    for (int o = tid; o < 480; o += 192) {
        int which = o / 160, oo = o - which * 160;
        const float* W; const float* Bv; const float* xs; __half* O;
        if (which == 0)      { W = w5; Bv = b5; xs = fwu; O = out5; }
        else if (which == 1) { W = w6; Bv = b6; xs = fwe; O = out6; }
        else                 { W = w7; Bv = b7; xs = obs; O = out7; }
        float acc = Bv[oo];
        const float* wr = W + oo * 32;
        #pragma unroll
        for (int k = 0; k < 32; k++) acc += xs[k] * wr[k];
        O[b * 160 + oo] = __float2half(fmaxf(acc, 0.f));
    }
}

// ---------------- FP16-storage tensor-core multi-segment GEMM ----------------
// BM=64 BN=64 BK=32(halves), 128 threads (2x2 warps, warp 32x32), 2-stage cp.async,
// ldmatrix fragment loads.
// lstmH >0          : fused LSTM cell epilogue (weights pre-interleaved; bias mapped here).
// lstmH==0, act<2   : Zh = act(sum + bias0) as fp16.
// lstmH==0, act==2  : KF epilogue -> f32 out.
struct GSeg {
    const __half* X;   // [BB, K] fp16 contiguous
    const __half* W;   // fp16 row-major, row stride ldw (may carry column offset)
    int K;
    int ldw;
};

#define LDAH 40   // halves; row stride 80B -> conflict-free ldmatrix/staging

__device__ __forceinline__ void cpa16(void* s, const void* g) {
    uint32_t sa = (uint32_t)__cvta_generic_to_shared(s);
    asm volatile("cp.async.cg.shared.global [%0], [%1], 16;\n" :: "r"(sa), "l"(g));
}
__device__ __forceinline__ void ldm_x4(uint32_t* r, const __half* p) {
    uint32_t a = (uint32_t)__cvta_generic_to_shared(p);
    asm volatile("ldmatrix.sync.aligned.m8n8.x4.shared.b16 {%0,%1,%2,%3}, [%4];"
                 : "=r"(r[0]), "=r"(r[1]), "=r"(r[2]), "=r"(r[3]) : "r"(a));
}

__global__ void __launch_bounds__(128) gemm_tc(
    GSeg s0, GSeg s1, GSeg s2, int nseg,
    const float* __restrict__ bias0, const float* __restrict__ bias1,
    __half* __restrict__ Zh, int Nout, int act,
    int lstmH, float* __restrict__ cst, __half* __restrict__ hH,
    const float* __restrict__ dyp, const float* __restrict__ xpr,
    float* __restrict__ outp)
{
    __shared__ __half As[2][64 * LDAH];
    __shared__ __half Bs[2][64 * LDAH];

    int tid  = threadIdx.x;
    int lane = tid & 31;
    int wid  = tid >> 5;
    int wm   = wid & 1;
    int wn   = wid >> 1;
    int gid  = lane >> 2;
    int tg   = lane & 3;

    int row0 = blockIdx.y * 64;
    int col0 = blockIdx.x * 64;

    // staging: rows srow, srow+32; chunk scol (8 halves = 16B)
    int srow = tid >> 2;          // 0..31
    int scol = (tid & 3) * 8;     // 0,8,16,24

    // ldmatrix per-lane offsets
    int lt   = lane >> 3;         // tile idx 0..3
    int lrow = lane & 7;
    int aRowOff = ((lt & 1) * 8 + lrow);   // within 16-row tile pair
    int aKOff   = (lt >> 1) * 8;
    int bRowOff = ((lt >> 1) * 8 + lrow);
    int bKOff   = (lt & 1) * 8;

    int totK = s0.K + ((nseg > 1) ? s1.K : 0) + ((nseg > 2) ? s2.K : 0);
    int niter = totK >> 5;

    float c[2][4][4];
    #pragma unroll
    for (int mt = 0; mt < 2; mt++)
        #pragma unroll
        for (int nt = 0; nt < 4; nt++)
            #pragma unroll
            for (int r = 0; r < 4; r++) c[mt][nt][r] = 0.f;

    auto issue = [&](int it, int p) {
        int kb = it << 5;
        const __half* X = s0.X; const __half* W = s0.W; int K = s0.K; int ldw = s0.ldw;
        if (kb >= s0.K) {
            kb -= s0.K;
            if (nseg > 2 && kb >= s1.K) { kb -= s1.K; X = s2.X; W = s2.W; K = s2.K; ldw = s2.ldw; }
            else                        {             X = s1.X; W = s1.W; K = s1.K; ldw = s1.ldw; }
        }
        #pragma unroll
        for (int i = 0; i < 2; i++) {
            int r = srow + 32 * i;
            cpa16(&As[p][r * LDAH + scol], X + (size_t)(row0 + r) * K + kb + scol);
            cpa16(&Bs[p][r * LDAH + scol], W + (size_t)(col0 + r) * ldw + kb + scol);
        }
        asm volatile("cp.async.commit_group;\n" ::);
    };

    issue(0, 0);

    for (int it = 0; it < niter; it++) {
        int p = it & 1;
        if (it + 1 < niter) {
            issue(it + 1, p ^ 1);
            asm volatile("cp.async.wait_group 1;\n" ::);
        } else {
            asm volatile("cp.async.wait_group 0;\n" ::);
        }
        __syncthreads();

        #pragma unroll
        for (int ks = 0; ks < 2; ks++) {
            int kk = ks * 16;
            uint32_t af[2][4];
            #pragma unroll
            for (int mt = 0; mt < 2; mt++) {
                int r = wm * 32 + mt * 16 + aRowOff;
                ldm_x4(af[mt], &As[p][r * LDAH + kk + aKOff]);
            }
            uint32_t bf[4][2];
            #pragma unroll
            for (int ntp = 0; ntp < 2; ntp++) {
                int n = wn * 32 + ntp * 16 + bRowOff;
                uint32_t tmp[4];
                ldm_x4(tmp, &Bs[p][n * LDAH + kk + bKOff]);
                bf[2 * ntp][0]     = tmp[0];
                bf[2 * ntp][1]     = tmp[1];
                bf[2 * ntp + 1][0] = tmp[2];
                bf[2 * ntp + 1][1] = tmp[3];
            }
            #pragma unroll
            for (int mt = 0; mt < 2; mt++)
                #pragma unroll
                for (int nt = 0; nt < 4; nt++) {
                    asm volatile(
                        "mma.sync.aligned.m16n8k16.row.col.f32.f16.f16.f32 "
                        "{%0,%1,%2,%3}, {%4,%5,%6,%7}, {%8,%9}, {%0,%1,%2,%3};\n"
                        : "+f"(c[mt][nt][0]), "+f"(c[mt][nt][1]),
                          "+f"(c[mt][nt][2]), "+f"(c[mt][nt][3])
                        : "r"(af[mt][0]), "r"(af[mt][1]), "r"(af[mt][2]), "r"(af[mt][3]),
                          "r"(bf[nt][0]), "r"(bf[nt][1]));
                }
        }
        __syncthreads();
    }

    if (lstmH > 0) {
        // fused LSTM cell: lane tg even holds (i,f) of unit j, lane tg^1 holds (g,o)
        const int H = lstmH;
        #pragma unroll
        for (int mt = 0; mt < 2; mt++) {
            int r = row0 + wm * 32 + mt * 16 + gid;
            #pragma unroll
            for (int nt = 0; nt < 4; nt++) {
                int cb = col0 + wn * 32 + nt * 8 + tg * 2;   // logical col (j*4+g)
                int ro0 = (cb & 3) * H + (cb >> 2);
                int ro1 = ((cb + 1) & 3) * H + ((cb + 1) >> 2);
                float b0a = bias0[ro0] + bias1[ro0];
                float b0b = bias0[ro1] + bias1[ro1];
                float z0 = c[mt][nt][0] + b0a;
                float z1 = c[mt][nt][1] + b0b;
                float z2 = c[mt][nt][2] + b0a;
                float z3 = c[mt][nt][3] + b0b;
                float p0 = __shfl_xor_sync(0xffffffffu, z0, 1);
                float p1 = __shfl_xor_sync(0xffffffffu, z1, 1);
                float p2 = __shfl_xor_sync(0xffffffffu, z2, 1);
                float p3 = __shfl_xor_sync(0xffffffffu, z3, 1);
                if ((tg & 1) == 0) {
                    int jj = cb >> 2;
                    {
                        float si = sigmoidf(z0), sf = sigmoidf(z1);
                        float gg = tanhf(p0),    so = sigmoidf(p1);
                        float cn = sf * cst[(size_t)r * H + jj] + si * gg;
                        cst[(size_t)r * H + jj] = cn;
                        hH[(size_t)r * H + jj] = __float2half(so * tanhf(cn));
                    }
                    {
                        float si = sigmoidf(z2), sf = sigmoidf(z3);
                        float gg = tanhf(p2),    so = sigmoidf(p3);
                        float cn = sf * cst[(size_t)(r + 8) * H + jj] + si * gg;
                        cst[(size_t)(r + 8) * H + jj] = cn;
                        hH[(size_t)(r + 8) * H + jj] = __float2half(so * tanhf(cn));
                    }
                }
            }
        }
    } else if (act == 2) {
        // fused KF update: warp's 32-col strip = K rows mbase, mbase+1
        int mbase = (col0 >> 4) + wn * 2;
        #pragma unroll
        for (int mt = 0; mt < 2; mt++) {
            int r = row0 + wm * 32 + mt * 16 + gid;
            float accA0 = 0.f, accA1 = 0.f;
            float accB0 = 0.f, accB1 = 0.f;
            #pragma unroll
            for (int nt = 0; nt < 4; nt++) {
                int n = (nt & 1) * 8 + tg * 2;
                int cbg = col0 + wn * 32 + nt * 8 + tg * 2;
                float b0 = bias0[cbg], b1 = bias0[cbg + 1];
                float d0 = dyp[r * NN + n],       d1 = dyp[r * NN + n + 1];
                float d2 = dyp[(r + 8) * NN + n], d3 = dyp[(r + 8) * NN + n + 1];
                float t0 = (c[mt][nt][0] + b0) * d0 + (c[mt][nt][1] + b1) * d1;
                float t1 = (c[mt][nt][2] + b0) * d2 + (c[mt][nt][3] + b1) * d3;
                if (nt < 2) { accA0 += t0; accA1 += t1; }
                else        { accB0 += t0; accB1 += t1; }
            }
            accA0 += __shfl_xor_sync(0xffffffffu, accA0, 1);
            accA0 += __shfl_xor_sync(0xffffffffu, accA0, 2);
            accA1 += __shfl_xor_sync(0xffffffffu, accA1, 1);
            accA1 += __shfl_xor_sync(0xffffffffu, accA1, 2);
            accB0 += __shfl_xor_sync(0xffffffffu, accB0, 1);
            accB0 += __shfl_xor_sync(0xffffffffu, accB0, 2);
            accB1 += __shfl_xor_sync(0xffffffffu, accB1, 1);
            accB1 += __shfl_xor_sync(0xffffffffu, accB1, 2);
            if (tg == 0) {
                int m0 = mbase, m1 = mbase + 1;
                outp[r * MM + m0]       = xpr[r * MM + m0]       + accA0;
                outp[(r + 8) * MM + m0] = xpr[(r + 8) * MM + m0] + accA1;
                outp[r * MM + m1]       = xpr[r * MM + m1]       + accB0;
                outp[(r + 8) * MM + m1] = xpr[(r + 8) * MM + m1] + accB1;
            }
        }
    } else {
        #pragma unroll
        for (int mt = 0; mt < 2; mt++) {
            int r = row0 + wm * 32 + mt * 16 + gid;
            #pragma unroll
            for (int nt = 0; nt < 4; nt++) {
                int cb = col0 + wn * 32 + nt * 8 + tg * 2;
                float b0a = bias0[cb], b0b = bias0[cb + 1];
                float v0 = c[mt][nt][0] + b0a;
                float v1 = c[mt][nt][1] + b0b;
                float v2 = c[mt][nt][2] + b0a;
                float v3 = c[mt][nt][3] + b0b;
                if (act) {
                    v0 = fmaxf(v0, 0.f); v1 = fmaxf(v1, 0.f);
                    v2 = fmaxf(v2, 0.f); v3 = fmaxf(v3, 0.f);
                }
                *reinterpret_cast<__half2*>(&Zh[(size_t)r * Nout + cb]) =
                    __floats2half2_rn(v0, v1);
                *reinterpret_cast<__half2*>(&Zh[(size_t)(r + 8) * Nout + cb]) =
                    __floats2half2_rn(v2, v3);
            }
        }
    }
}

// ---------------- host orchestration ----------------
extern "C" void kernel_launch(void* const* d_in, const int* in_sizes, int n_in,
                              void* d_out, int out_size)
{
    const float* Y       = (const float*)d_in[0];
    const float* x0      = (const float*)d_in[1];
    const float* Wq_ih   = (const float*)d_in[2];
    const float* Wq_hh   = (const float*)d_in[3];
    const float* bq_ih   = (const float*)d_in[4];
    const float* bq_hh   = (const float*)d_in[5];
    const float* Wsig_ih = (const float*)d_in[6];
    const float* Wsig_hh = (const float*)d_in[7];
    const float* bsig_ih = (const float*)d_in[8];
    const float* bsig_hh = (const float*)d_in[9];
    const float* Ws_ih   = (const float*)d_in[10];
    const float* Ws_hh   = (const float*)d_in[11];
    const float* bs_ih   = (const float*)d_in[12];
    const float* bs_hh   = (const float*)d_in[13];
    const float* fc1_w   = (const float*)d_in[14];
    const float* fc1_b   = (const float*)d_in[15];
    const float* fc2a_w  = (const float*)d_in[16];
    const float* fc2a_b  = (const float*)d_in[17];
    const float* fc2b_w  = (const float*)d_in[18];
    const float* fc2b_b  = (const float*)d_in[19];
    const float* fc5_w   = (const float*)d_in[20];
    const float* fc5_b   = (const float*)d_in[21];
    const float* fc6_w   = (const float*)d_in[22];
    const float* fc6_b   = (const float*)d_in[23];
    const float* fc7_w   = (const float*)d_in[24];
    const float* fc7_b   = (const float*)d_in[25];

    float* out = (float*)d_out;   // [T, B, M, 1]

    __half *WqihH, *WqhhH, *WsigihH, *WsighhH, *WsihH, *WshhH, *fc1H, *fc2aH, *fc2bH;
    __half *hQ0, *hSig0, *hS0, *out5, *out6, *out7, *out1, *a2;
    float *cQ, *cSig, *cS, *xprior0, *dy, *yprev0;
    cudaGetSymbolAddress((void**)&WqihH,   g_WqihH);
    cudaGetSymbolAddress((void**)&WqhhH,   g_WqhhH);
    cudaGetSymbolAddress((void**)&WsigihH, g_WsigihH);
    cudaGetSymbolAddress((void**)&WsighhH, g_WsighhH);
    cudaGetSymbolAddress((void**)&WsihH,   g_WsihH);
    cudaGetSymbolAddress((void**)&WshhH,   g_WshhH);
    cudaGetSymbolAddress((void**)&fc1H,    g_fc1H);
    cudaGetSymbolAddress((void**)&fc2aH,   g_fc2aH);
    cudaGetSymbolAddress((void**)&fc2bH,   g_fc2bH);
    cudaGetSymbolAddress((void**)&hQ0,     g_hQh);
    cudaGetSymbolAddress((void**)&hSig0,   g_hSigh);
    cudaGetSymbolAddress((void**)&hS0,     g_hSh);
    cudaGetSymbolAddress((void**)&out5,    g_out5h);
    cudaGetSymbolAddress((void**)&out6,    g_out6h);
    cudaGetSymbolAddress((void**)&out7,    g_out7h);
    cudaGetSymbolAddress((void**)&out1,    g_out1h);
    cudaGetSymbolAddress((void**)&a2,      g_a2h);
    cudaGetSymbolAddress((void**)&cQ,      g_cQ);
    cudaGetSymbolAddress((void**)&cSig,    g_cSig);
    cudaGetSymbolAddress((void**)&cS,      g_cS);
    cudaGetSymbolAddress((void**)&xprior0, g_xprior);
    cudaGetSymbolAddress((void**)&dy,      g_dy);
    cudaGetSymbolAddress((void**)&yprev0,  g_yprev0);

    __half* hQ[2]   = {hQ0,   hQ0   + BB * HQ};
    __half* hSig[2] = {hSig0, hSig0 + BB * HQ};
    __half* hS[2]   = {hS0,   hS0   + BB * HS};
    float* xprior_buf[2] = {xprior0, xprior0 + BB * MM};

    const GSeg nil = {nullptr, nullptr, 0, 0};

    // per-replay weight conversion (9 independent launches, graph head)
    cvt_w<<<4 * HQ, 128>>>(Wq_ih,   WqihH,   D_Q_IN,   HQ);
    cvt_w<<<4 * HQ, 128>>>(Wq_hh,   WqhhH,   HQ,       HQ);
    cvt_w<<<4 * HQ, 128>>>(Wsig_ih, WsigihH, D_SIG_IN, HQ);
    cvt_w<<<4 * HQ, 128>>>(Wsig_hh, WsighhH, HQ,       HQ);
    cvt_w<<<4 * HS, 128>>>(Ws_ih,   WsihH,   D_S_IN,   HS);
    cvt_w<<<4 * HS, 128>>>(Ws_hh,   WshhH,   HS,       HS);
    cvt_w<<<HS, 128>>>(fc1_w, fc1H, HQ, 0);
    cvt_w<<<D_FC2_H, 128>>>(fc2a_w, fc2aH, D_FC2_IN, 0);
    cvt_w<<<NN * MM, 128>>>(fc2b_w, fc2bH, D_FC2_H, 0);

    init_kernel<<<(BB * HQ + 255) / 256, 256>>>(x0, yprev0);

    for (int t = 0; t < TT; t++) {
        const float* x_post      = (t == 0) ? x0 : out + (size_t)(t - 1) * BB * MM;
        const float* x_post_prev = (t <= 1) ? x0 : out + (size_t)(t - 2) * BB * MM;
        const float* x_prior_prev= (t == 0) ? x0 : xprior_buf[(t - 1) & 1];
        const float* y_t         = Y + (size_t)t * BB * NN;
        const float* y_prev      = (t == 0) ? yprev0 : Y + (size_t)(t - 1) * BB * NN;
        float* x_prior           = xprior_buf[t & 1];
        int rd = t & 1, wr = rd ^ 1;

        pre_fc_kernel<<<BB, 192>>>(x_post, x_post_prev, x_prior_prev, y_t, y_prev,
                                   x_prior, dy,
                                   fc5_w, fc5_b, fc6_w, fc6_b, fc7_w, fc7_b,
                                   out5, out6, out7);

        // LSTM Q
        {
            GSeg a = {out5,   WqihH, D_Q_IN, D_Q_IN};
            GSeg b = {hQ[rd], WqhhH, HQ,     HQ};
            gemm_tc<<<dim3(4 * HQ / 64, BB / 64), 128>>>(a, b, nil, 2, bq_ih, bq_hh,
                nullptr, 0, 0, HQ, cQ, hQ[wr], nullptr, nullptr, nullptr);
        }

        // LSTM Sigma: input = concat(hQ_new, out6)
        {
            GSeg a = {hQ[wr],   WsigihH,      HQ,     D_SIG_IN};
            GSeg b = {out6,     WsigihH + HQ, D_Q_IN, D_SIG_IN};
            GSeg c = {hSig[rd], WsighhH,      HQ,     HQ};
            gemm_tc<<<dim3(4 * HQ / 64, BB / 64), 128>>>(a, b, c, 3, bsig_ih, bsig_hh,
                nullptr, 0, 0, HQ, cSig, hSig[wr], nullptr, nullptr, nullptr);
        }

        // fc1
        {
            GSeg a = {hSig[wr], fc1H, HQ, HQ};
            gemm_tc<<<dim3(HS / 64, BB / 64), 128>>>(a, nil, nil, 1, fc1_b, nullptr,
                out1, HS, 1, 0, nullptr, nullptr, nullptr, nullptr, nullptr);
        }

        // LSTM S: input = concat(out1, out7)
        {
            GSeg a = {out1,   WsihH,      HS,     D_S_IN};
            GSeg b = {out7,   WsihH + HS, D_Q_IN, D_S_IN};
            GSeg c = {hS[rd], WshhH,      HS,     HS};
            gemm_tc<<<dim3(4 * HS / 64, BB / 64), 128>>>(a, b, c, 3, bs_ih, bs_hh,
                nullptr, 0, 0, HS, cS, hS[wr], nullptr, nullptr, nullptr);
        }

        // fc2a
        {
            GSeg a = {hSig[wr], fc2aH,      HQ, D_FC2_IN};
            GSeg b = {hS[wr],   fc2aH + HQ, HS, D_FC2_IN};
            gemm_tc<<<dim3(D_FC2_H / 64, BB / 64), 128>>>(a, b, nil, 2, fc2a_b, nullptr,
                a2, D_FC2_H, 1, 0, nullptr, nullptr, nullptr, nullptr, nullptr);
        }

        // fc2b + fused KF update
        {
            GSeg a = {a2, fc2bH, D_FC2_H, D_FC2_H};
            gemm_tc<<<dim3(NN * MM / 64, BB / 64), 128>>>(a, nil, nil, 1, fc2b_b, nullptr,
                nullptr, MM, 2, 0, nullptr, nullptr, dy, x_prior,
                out + (size_t)t * BB * MM);
        }
    }
}

// round 12
// speedup vs baseline: 2.7048x; 1.2087x over previous
#include <cuda_runtime.h>
#include <cuda_bf16.h>
#include <cuda_fp16.h>
#include <math.h>
#include <stdint.h>

// ---------------- problem constants ----------------
#define MM   32
#define NN   16
#define BB   256
#define TT   8
#define HQ   1024
#define HS   256
#define D_Q_IN   160
#define D_SIG_IN 1184
#define D_S_IN   416
#define D_FC2_IN 1280
#define D_FC2_H  2560

// ---------------- device scratch ----------------
// fp16 weights (LSTM ones gate-interleaved: dst row j*4+g <- src row g*H+j)
__device__ __half g_WqihH [4 * HQ * D_Q_IN];
__device__ __half g_WqhhH [4 * HQ * HQ];
__device__ __half g_WsigihH[4 * HQ * D_SIG_IN];
__device__ __half g_WsighhH[4 * HQ * HQ];
__device__ __half g_WsihH [4 * HS * D_S_IN];
__device__ __half g_WshhH [4 * HS * HS];
__device__ __half g_fc1H  [HS * HQ];
__device__ __half g_fc2aH [D_FC2_H * D_FC2_IN];
__device__ __half g_fc2bH [NN * MM * D_FC2_H];
// fp16 activations
__device__ __half g_hQh  [2][BB * HQ];
__device__ __half g_hSigh[2][BB * HQ];
__device__ __half g_hSh  [2][BB * HS];
__device__ __half g_out5h[BB * D_Q_IN];
__device__ __half g_out6h[BB * D_Q_IN];
__device__ __half g_out7h[BB * D_Q_IN];
__device__ __half g_out1h[BB * HS];
__device__ __half g_a2h  [BB * D_FC2_H];
// fp32 state
__device__ float g_cQ  [BB * HQ];
__device__ float g_cSig[BB * HQ];
__device__ float g_cS  [BB * HS];
__device__ float g_xprior[2][BB * MM];
__device__ float g_dy   [BB * NN];
__device__ float g_yprev0[BB * NN];

__device__ __forceinline__ float sigmoidf(float x) { return 1.f / (1.f + expf(-x)); }

// ---------------- weight f32->f16 (+optional gate interleave) ----------------
__global__ void cvt_w(const float* __restrict__ src, __half* __restrict__ dst,
                      int K, int H)   // grid.x = dst rows; H=0 -> identity row map
{
    int rp = blockIdx.x;
    int ro = H ? ((rp & 3) * H + (rp >> 2)) : rp;
    const float2* s = (const float2*)(src + (size_t)ro * K);
    __half2* d = (__half2*)(dst + (size_t)rp * K);
    for (int k = threadIdx.x; k < (K >> 1); k += blockDim.x) {
        float2 v = s[k];
        d[k] = __floats2half2_rn(v.x, v.y);
    }
}

// ---------------- init: zero states, y_prev0 = tanh(x0[:, :16]) ----------------
__global__ void init_kernel(const float* __restrict__ x0, float* __restrict__ yprev0)
{
    int idx = blockIdx.x * blockDim.x + threadIdx.x;
    __half hz = __float2half(0.f);
    if (idx < BB * HQ) {
        g_hQh[0][idx] = hz; g_hQh[1][idx] = hz; g_cQ[idx] = 0.f;
        g_hSigh[0][idx] = hz; g_hSigh[1][idx] = hz; g_cSig[idx] = 0.f;
    }
    if (idx < BB * HS) { g_hSh[0][idx] = hz; g_hSh[1][idx] = hz; g_cS[idx] = 0.f; }
    if (idx < BB * NN) {
        int b = idx / NN, n = idx % NN;
        yprev0[idx] = tanhf(x0[b * MM + n]);
    }
}

// ---------------- fused prologue + fc5/6/7 (fp16 outputs) ----------------
__global__ void pre_fc_kernel(const float* __restrict__ x_post,
                              const float* __restrict__ x_post_prev,
                              const float* __restrict__ x_prior_prev,
                              const float* __restrict__ y_t,
                              const float* __restrict__ y_prev,
                              float* __restrict__ x_prior,
                              float* __restrict__ dy_buf,
                              const float* __restrict__ w5, const float* __restrict__ b5,
                              const float* __restrict__ w6, const float* __restrict__ b6,
                              const float* __restrict__ w7, const float* __restrict__ b7,
                              __half* __restrict__ out5,
                              __half* __restrict__ out6,
                              __half* __restrict__ out7)
{
    int b = blockIdx.x;
    int tid = threadIdx.x;
    __shared__ float fwu[32], fwe[32], obs[32];

    if (tid < 32) {
        int lane = tid;
        float xp   = x_post[b * MM + lane];
        float xpp  = x_post_prev[b * MM + lane];
        float xprp = x_prior_prev[b * MM + lane];

        float xpr = xp + 0.1f * sinf(xp);
        x_prior[b * MM + lane] = xpr;

        float de = xp - xpp;
        float du = xp - xprp;
        float se = de * de, su = du * du;
        #pragma unroll
        for (int o = 16; o > 0; o >>= 1) {
            se += __shfl_xor_sync(0xffffffffu, se, o);
            su += __shfl_xor_sync(0xffffffffu, su, o);
        }
        fwe[lane] = de / fmaxf(sqrtf(se), 1e-12f);
        fwu[lane] = du / fmaxf(sqrtf(su), 1e-12f);

        float y     = (lane < NN) ? y_t[b * NN + lane]    : 0.f;
        float ypv   = (lane < NN) ? y_prev[b * NN + lane] : 0.f;
        float ypred = (lane < NN) ? tanhf(xpr)            : 0.f;
        float d1 = y - ypv;
        float d2 = y - ypred;
        if (lane < NN) dy_buf[b * NN + lane] = d2;
        float s1 = d1 * d1, s2 = d2 * d2;
        #pragma unroll
        for (int o = 16; o > 0; o >>= 1) {
            s1 += __shfl_xor_sync(0xffffffffu, s1, o);
            s2 += __shfl_xor_sync(0xffffffffu, s2, o);
        }
        if (lane < NN) {
            obs[lane]      = d1 / fmaxf(sqrtf(s1), 1e-12f);
            obs[NN + lane] = d2 / fmaxf(sqrtf(s2), 1e-12f);
        }
    }
    __syncthreads();

    for (int o = tid; o < 480; o += 192) {
        int which = o / 160, oo = o - which * 160;
        const float* W; const float* Bv; const float* xs; __half* O;
        if (which == 0)      { W = w5; Bv = b5; xs = fwu; O = out5; }
        else if (which == 1) { W = w6; Bv = b6; xs = fwe; O = out6; }
        else                 { W = w7; Bv = b7; xs = obs; O = out7; }
        float acc = Bv[oo];
        const float* wr = W + oo * 32;
        #pragma unroll
        for (int k = 0; k < 32; k++) acc += xs[k] * wr[k];
        O[b * 160 + oo] = __float2half(fmaxf(acc, 0.f));
    }
}

// ---------------- FP16-storage tensor-core multi-segment GEMM ----------------
// BM=64 BN=64 BK=32(halves), 128 threads (2x2 warps, warp 32x32),
// 4-stage cp.async pipeline with ONE __syncthreads per iteration, ldmatrix loads.
// lstmH >0          : fused LSTM cell epilogue (weights pre-interleaved; bias mapped here).
// lstmH==0, act<2   : Zh = act(sum + bias0) as fp16.
// lstmH==0, act==2  : KF epilogue -> f32 out.
struct GSeg {
    const __half* X;   // [BB, K] fp16 contiguous
    const __half* W;   // fp16 row-major, row stride ldw (may carry column offset)
    int K;
    int ldw;
};

#define LDAH 40   // halves; row stride 80B -> conflict-free ldmatrix/staging
#define NSTAGE 4

__device__ __forceinline__ void cpa16(void* s, const void* g) {
    uint32_t sa = (uint32_t)__cvta_generic_to_shared(s);
    asm volatile("cp.async.cg.shared.global [%0], [%1], 16;\n" :: "r"(sa), "l"(g));
}
__device__ __forceinline__ void ldm_x4(uint32_t* r, const __half* p) {
    uint32_t a = (uint32_t)__cvta_generic_to_shared(p);
    asm volatile("ldmatrix.sync.aligned.m8n8.x4.shared.b16 {%0,%1,%2,%3}, [%4];"
                 : "=r"(r[0]), "=r"(r[1]), "=r"(r[2]), "=r"(r[3]) : "r"(a));
}

__global__ void __launch_bounds__(128) gemm_tc(
    GSeg s0, GSeg s1, GSeg s2, int nseg,
    const float* __restrict__ bias0, const float* __restrict__ bias1,
    __half* __restrict__ Zh, int Nout, int act,
    int lstmH, float* __restrict__ cst, __half* __restrict__ hH,
    const float* __restrict__ dyp, const float* __restrict__ xpr,
    float* __restrict__ outp)
{
    __shared__ __half As[NSTAGE][64 * LDAH];
    __shared__ __half Bs[NSTAGE][64 * LDAH];

    int tid  = threadIdx.x;
    int lane = tid & 31;
    int wid  = tid >> 5;
    int wm   = wid & 1;
    int wn   = wid >> 1;
    int gid  = lane >> 2;
    int tg   = lane & 3;

    int row0 = blockIdx.y * 64;
    int col0 = blockIdx.x * 64;

    // staging: rows srow, srow+32; chunk scol (8 halves = 16B)
    int srow = tid >> 2;          // 0..31
    int scol = (tid & 3) * 8;     // 0,8,16,24

    // ldmatrix per-lane offsets
    int lt   = lane >> 3;         // tile idx 0..3
    int lrow = lane & 7;
    int aRowOff = ((lt & 1) * 8 + lrow);
    int aKOff   = (lt >> 1) * 8;
    int bRowOff = ((lt >> 1) * 8 + lrow);
    int bKOff   = (lt & 1) * 8;

    int totK = s0.K + ((nseg > 1) ? s1.K : 0) + ((nseg > 2) ? s2.K : 0);
    int niter = totK >> 5;

    float c[2][4][4];
    #pragma unroll
    for (int mt = 0; mt < 2; mt++)
        #pragma unroll
        for (int nt = 0; nt < 4; nt++)
            #pragma unroll
            for (int r = 0; r < 4; r++) c[mt][nt][r] = 0.f;

    auto issue = [&](int it, int p) {
        int kb = it << 5;
        const __half* X = s0.X; const __half* W = s0.W; int K = s0.K; int ldw = s0.ldw;
        if (kb >= s0.K) {
            kb -= s0.K;
            if (nseg > 2 && kb >= s1.K) { kb -= s1.K; X = s2.X; W = s2.W; K = s2.K; ldw = s2.ldw; }
            else                        {             X = s1.X; W = s1.W; K = s1.K; ldw = s1.ldw; }
        }
        #pragma unroll
        for (int i = 0; i < 2; i++) {
            int r = srow + 32 * i;
            cpa16(&As[p][r * LDAH + scol], X + (size_t)(row0 + r) * K + kb + scol);
            cpa16(&Bs[p][r * LDAH + scol], W + (size_t)(col0 + r) * ldw + kb + scol);
        }
        asm volatile("cp.async.commit_group;\n" ::);
    };

    // prologue: fill stages 0..2 (empty commits keep group accounting uniform)
    #pragma unroll
    for (int i = 0; i < NSTAGE - 1; i++) {
        if (i < niter) issue(i, i);
        else asm volatile("cp.async.commit_group;\n" ::);
    }

    for (int it = 0; it < niter; it++) {
        int p = it & (NSTAGE - 1);
        asm volatile("cp.async.wait_group %0;\n" :: "n"(NSTAGE - 2));
        __syncthreads();
        // prefetch stage it+3 into slot (it-1)%4 — safe: all warps completed compute(it-1)
        if (it + NSTAGE - 1 < niter) issue(it + NSTAGE - 1, (it + NSTAGE - 1) & (NSTAGE - 1));
        else asm volatile("cp.async.commit_group;\n" ::);

        #pragma unroll
        for (int ks = 0; ks < 2; ks++) {
            int kk = ks * 16;
            uint32_t af[2][4];
            #pragma unroll
            for (int mt = 0; mt < 2; mt++) {
                int r = wm * 32 + mt * 16 + aRowOff;
                ldm_x4(af[mt], &As[p][r * LDAH + kk + aKOff]);
            }
            uint32_t bf[4][2];
            #pragma unroll
            for (int ntp = 0; ntp < 2; ntp++) {
                int n = wn * 32 + ntp * 16 + bRowOff;
                uint32_t tmp[4];
                ldm_x4(tmp, &Bs[p][n * LDAH + kk + bKOff]);
                bf[2 * ntp][0]     = tmp[0];
                bf[2 * ntp][1]     = tmp[1];
                bf[2 * ntp + 1][0] = tmp[2];
                bf[2 * ntp + 1][1] = tmp[3];
            }
            #pragma unroll
            for (int mt = 0; mt < 2; mt++)
                #pragma unroll
                for (int nt = 0; nt < 4; nt++) {
                    asm volatile(
                        "mma.sync.aligned.m16n8k16.row.col.f32.f16.f16.f32 "
                        "{%0,%1,%2,%3}, {%4,%5,%6,%7}, {%8,%9}, {%0,%1,%2,%3};\n"
                        : "+f"(c[mt][nt][0]), "+f"(c[mt][nt][1]),
                          "+f"(c[mt][nt][2]), "+f"(c[mt][nt][3])
                        : "r"(af[mt][0]), "r"(af[mt][1]), "r"(af[mt][2]), "r"(af[mt][3]),
                          "r"(bf[nt][0]), "r"(bf[nt][1]));
                }
        }
    }

    if (lstmH > 0) {
        // fused LSTM cell: lane tg even holds (i,f) of unit j, lane tg^1 holds (g,o)
        const int H = lstmH;
        #pragma unroll
        for (int mt = 0; mt < 2; mt++) {
            int r = row0 + wm * 32 + mt * 16 + gid;
            #pragma unroll
            for (int nt = 0; nt < 4; nt++) {
                int cb = col0 + wn * 32 + nt * 8 + tg * 2;   // logical col (j*4+g)
                int ro0 = (cb & 3) * H + (cb >> 2);
                int ro1 = ((cb + 1) & 3) * H + ((cb + 1) >> 2);
                float b0a = bias0[ro0] + bias1[ro0];
                float b0b = bias0[ro1] + bias1[ro1];
                float z0 = c[mt][nt][0] + b0a;
                float z1 = c[mt][nt][1] + b0b;
                float z2 = c[mt][nt][2] + b0a;
                float z3 = c[mt][nt][3] + b0b;
                float p0 = __shfl_xor_sync(0xffffffffu, z0, 1);
                float p1 = __shfl_xor_sync(0xffffffffu, z1, 1);
                float p2 = __shfl_xor_sync(0xffffffffu, z2, 1);
                float p3 = __shfl_xor_sync(0xffffffffu, z3, 1);
                if ((tg & 1) == 0) {
                    int jj = cb >> 2;
                    {
                        float si = sigmoidf(z0), sf = sigmoidf(z1);
                        float gg = tanhf(p0),    so = sigmoidf(p1);
                        float cn = sf * cst[(size_t)r * H + jj] + si * gg;
                        cst[(size_t)r * H + jj] = cn;
                        hH[(size_t)r * H + jj] = __float2half(so * tanhf(cn));
                    }
                    {
                        float si = sigmoidf(z2), sf = sigmoidf(z3);
                        float gg = tanhf(p2),    so = sigmoidf(p3);
                        float cn = sf * cst[(size_t)(r + 8) * H + jj] + si * gg;
                        cst[(size_t)(r + 8) * H + jj] = cn;
                        hH[(size_t)(r + 8) * H + jj] = __float2half(so * tanhf(cn));
                    }
                }
            }
        }
    } else if (act == 2) {
        // fused KF update: warp's 32-col strip = K rows mbase, mbase+1
        int mbase = (col0 >> 4) + wn * 2;
        #pragma unroll
        for (int mt = 0; mt < 2; mt++) {
            int r = row0 + wm * 32 + mt * 16 + gid;
            float accA0 = 0.f, accA1 = 0.f;
            float accB0 = 0.f, accB1 = 0.f;
            #pragma unroll
            for (int nt = 0; nt < 4; nt++) {
                int n = (nt & 1) * 8 + tg * 2;
                int cbg = col0 + wn * 32 + nt * 8 + tg * 2;
                float b0 = bias0[cbg], b1 = bias0[cbg + 1];
                float d0 = dyp[r * NN + n],       d1 = dyp[r * NN + n + 1];
                float d2 = dyp[(r + 8) * NN + n], d3 = dyp[(r + 8) * NN + n + 1];
                float t0 = (c[mt][nt][0] + b0) * d0 + (c[mt][nt][1] + b1) * d1;
                float t1 = (c[mt][nt][2] + b0) * d2 + (c[mt][nt][3] + b1) * d3;
                if (nt < 2) { accA0 += t0; accA1 += t1; }
                else        { accB0 += t0; accB1 += t1; }
            }
            accA0 += __shfl_xor_sync(0xffffffffu, accA0, 1);
            accA0 += __shfl_xor_sync(0xffffffffu, accA0, 2);
            accA1 += __shfl_xor_sync(0xffffffffu, accA1, 1);
            accA1 += __shfl_xor_sync(0xffffffffu, accA1, 2);
            accB0 += __shfl_xor_sync(0xffffffffu, accB0, 1);
            accB0 += __shfl_xor_sync(0xffffffffu, accB0, 2);
            accB1 += __shfl_xor_sync(0xffffffffu, accB1, 1);
            accB1 += __shfl_xor_sync(0xffffffffu, accB1, 2);
            if (tg == 0) {
                int m0 = mbase, m1 = mbase + 1;
                outp[r * MM + m0]       = xpr[r * MM + m0]       + accA0;
                outp[(r + 8) * MM + m0] = xpr[(r + 8) * MM + m0] + accA1;
                outp[r * MM + m1]       = xpr[r * MM + m1]       + accB0;
                outp[(r + 8) * MM + m1] = xpr[(r + 8) * MM + m1] + accB1;
            }
        }
    } else {
        #pragma unroll
        for (int mt = 0; mt < 2; mt++) {
            int r = row0 + wm * 32 + mt * 16 + gid;
            #pragma unroll
            for (int nt = 0; nt < 4; nt++) {
                int cb = col0 + wn * 32 + nt * 8 + tg * 2;
                float b0a = bias0[cb], b0b = bias0[cb + 1];
                float v0 = c[mt][nt][0] + b0a;
                float v1 = c[mt][nt][1] + b0b;
                float v2 = c[mt][nt][2] + b0a;
                float v3 = c[mt][nt][3] + b0b;
                if (act) {
                    v0 = fmaxf(v0, 0.f); v1 = fmaxf(v1, 0.f);
                    v2 = fmaxf(v2, 0.f); v3 = fmaxf(v3, 0.f);
                }
                *reinterpret_cast<__half2*>(&Zh[(size_t)r * Nout + cb]) =
                    __floats2half2_rn(v0, v1);
                *reinterpret_cast<__half2*>(&Zh[(size_t)(r + 8) * Nout + cb]) =
                    __floats2half2_rn(v2, v3);
            }
        }
    }
}

// ---------------- host orchestration ----------------
extern "C" void kernel_launch(void* const* d_in, const int* in_sizes, int n_in,
                              void* d_out, int out_size)
{
    const float* Y       = (const float*)d_in[0];
    const float* x0      = (const float*)d_in[1];
    const float* Wq_ih   = (const float*)d_in[2];
    const float* Wq_hh   = (const float*)d_in[3];
    const float* bq_ih   = (const float*)d_in[4];
    const float* bq_hh   = (const float*)d_in[5];
    const float* Wsig_ih = (const float*)d_in[6];
    const float* Wsig_hh = (const float*)d_in[7];
    const float* bsig_ih = (const float*)d_in[8];
    const float* bsig_hh = (const float*)d_in[9];
    const float* Ws_ih   = (const float*)d_in[10];
    const float* Ws_hh   = (const float*)d_in[11];
    const float* bs_ih   = (const float*)d_in[12];
    const float* bs_hh   = (const float*)d_in[13];
    const float* fc1_w   = (const float*)d_in[14];
    const float* fc1_b   = (const float*)d_in[15];
    const float* fc2a_w  = (const float*)d_in[16];
    const float* fc2a_b  = (const float*)d_in[17];
    const float* fc2b_w  = (const float*)d_in[18];
    const float* fc2b_b  = (const float*)d_in[19];
    const float* fc5_w   = (const float*)d_in[20];
    const float* fc5_b   = (const float*)d_in[21];
    const float* fc6_w   = (const float*)d_in[22];
    const float* fc6_b   = (const float*)d_in[23];
    const float* fc7_w   = (const float*)d_in[24];
    const float* fc7_b   = (const float*)d_in[25];

    float* out = (float*)d_out;   // [T, B, M, 1]

    __half *WqihH, *WqhhH, *WsigihH, *WsighhH, *WsihH, *WshhH, *fc1H, *fc2aH, *fc2bH;
    __half *hQ0, *hSig0, *hS0, *out5, *out6, *out7, *out1, *a2;
    float *cQ, *cSig, *cS, *xprior0, *dy, *yprev0;
    cudaGetSymbolAddress((void**)&WqihH,   g_WqihH);
    cudaGetSymbolAddress((void**)&WqhhH,   g_WqhhH);
    cudaGetSymbolAddress((void**)&WsigihH, g_WsigihH);
    cudaGetSymbolAddress((void**)&WsighhH, g_WsighhH);
    cudaGetSymbolAddress((void**)&WsihH,   g_WsihH);
    cudaGetSymbolAddress((void**)&WshhH,   g_WshhH);
    cudaGetSymbolAddress((void**)&fc1H,    g_fc1H);
    cudaGetSymbolAddress((void**)&fc2aH,   g_fc2aH);
    cudaGetSymbolAddress((void**)&fc2bH,   g_fc2bH);
    cudaGetSymbolAddress((void**)&hQ0,     g_hQh);
    cudaGetSymbolAddress((void**)&hSig0,   g_hSigh);
    cudaGetSymbolAddress((void**)&hS0,     g_hSh);
    cudaGetSymbolAddress((void**)&out5,    g_out5h);
    cudaGetSymbolAddress((void**)&out6,    g_out6h);
    cudaGetSymbolAddress((void**)&out7,    g_out7h);
    cudaGetSymbolAddress((void**)&out1,    g_out1h);
    cudaGetSymbolAddress((void**)&a2,      g_a2h);
    cudaGetSymbolAddress((void**)&cQ,      g_cQ);
    cudaGetSymbolAddress((void**)&cSig,    g_cSig);
    cudaGetSymbolAddress((void**)&cS,      g_cS);
    cudaGetSymbolAddress((void**)&xprior0, g_xprior);
    cudaGetSymbolAddress((void**)&dy,      g_dy);
    cudaGetSymbolAddress((void**)&yprev0,  g_yprev0);

    __half* hQ[2]   = {hQ0,   hQ0   + BB * HQ};
    __half* hSig[2] = {hSig0, hSig0 + BB * HQ};
    __half* hS[2]   = {hS0,   hS0   + BB * HS};
    float* xprior_buf[2] = {xprior0, xprior0 + BB * MM};

    const GSeg nil = {nullptr, nullptr, 0, 0};

    // per-replay weight conversion (9 independent launches, graph head)
    cvt_w<<<4 * HQ, 128>>>(Wq_ih,   WqihH,   D_Q_IN,   HQ);
    cvt_w<<<4 * HQ, 128>>>(Wq_hh,   WqhhH,   HQ,       HQ);
    cvt_w<<<4 * HQ, 128>>>(Wsig_ih, WsigihH, D_SIG_IN, HQ);
    cvt_w<<<4 * HQ, 128>>>(Wsig_hh, WsighhH, HQ,       HQ);
    cvt_w<<<4 * HS, 128>>>(Ws_ih,   WsihH,   D_S_IN,   HS);
    cvt_w<<<4 * HS, 128>>>(Ws_hh,   WshhH,   HS,       HS);
    cvt_w<<<HS, 128>>>(fc1_w, fc1H, HQ, 0);
    cvt_w<<<D_FC2_H, 128>>>(fc2a_w, fc2aH, D_FC2_IN, 0);
    cvt_w<<<NN * MM, 128>>>(fc2b_w, fc2bH, D_FC2_H, 0);

    init_kernel<<<(BB * HQ + 255) / 256, 256>>>(x0, yprev0);

    for (int t = 0; t < TT; t++) {
        const float* x_post      = (t == 0) ? x0 : out + (size_t)(t - 1) * BB * MM;
        const float* x_post_prev = (t <= 1) ? x0 : out + (size_t)(t - 2) * BB * MM;
        const float* x_prior_prev= (t == 0) ? x0 : xprior_buf[(t - 1) & 1];
        const float* y_t         = Y + (size_t)t * BB * NN;
        const float* y_prev      = (t == 0) ? yprev0 : Y + (size_t)(t - 1) * BB * NN;
        float* x_prior           = xprior_buf[t & 1];
        int rd = t & 1, wr = rd ^ 1;

        pre_fc_kernel<<<BB, 192>>>(x_post, x_post_prev, x_prior_prev, y_t, y_prev,
                                   x_prior, dy,
                                   fc5_w, fc5_b, fc6_w, fc6_b, fc7_w, fc7_b,
                                   out5, out6, out7);

        // LSTM Q
        {
            GSeg a = {out5,   WqihH, D_Q_IN, D_Q_IN};
            GSeg b = {hQ[rd], WqhhH, HQ,     HQ};
            gemm_tc<<<dim3(4 * HQ / 64, BB / 64), 128>>>(a, b, nil, 2, bq_ih, bq_hh,
                nullptr, 0, 0, HQ, cQ, hQ[wr], nullptr, nullptr, nullptr);
        }

        // LSTM Sigma: input = concat(hQ_new, out6)
        {
            GSeg a = {hQ[wr],   WsigihH,      HQ,     D_SIG_IN};
            GSeg b = {out6,     WsigihH + HQ, D_Q_IN, D_SIG_IN};
            GSeg c = {hSig[rd], WsighhH,      HQ,     HQ};
            gemm_tc<<<dim3(4 * HQ / 64, BB / 64), 128>>>(a, b, c, 3, bsig_ih, bsig_hh,
                nullptr, 0, 0, HQ, cSig, hSig[wr], nullptr, nullptr, nullptr);
        }

        // fc1
        {
            GSeg a = {hSig[wr], fc1H, HQ, HQ};
            gemm_tc<<<dim3(HS / 64, BB / 64), 128>>>(a, nil, nil, 1, fc1_b, nullptr,
                out1, HS, 1, 0, nullptr, nullptr, nullptr, nullptr, nullptr);
        }

        // LSTM S: input = concat(out1, out7)
        {
            GSeg a = {out1,   WsihH,      HS,     D_S_IN};
            GSeg b = {out7,   WsihH + HS, D_Q_IN, D_S_IN};
            GSeg c = {hS[rd], WshhH,      HS,     HS};
            gemm_tc<<<dim3(4 * HS / 64, BB / 64), 128>>>(a, b, c, 3, bs_ih, bs_hh,
                nullptr, 0, 0, HS, cS, hS[wr], nullptr, nullptr, nullptr);
        }

        // fc2a
        {
            GSeg a = {hSig[wr], fc2aH,      HQ, D_FC2_IN};
            GSeg b = {hS[wr],   fc2aH + HQ, HS, D_FC2_IN};
            gemm_tc<<<dim3(D_FC2_H / 64, BB / 64), 128>>>(a, b, nil, 2, fc2a_b, nullptr,
                a2, D_FC2_H, 1, 0, nullptr, nullptr, nullptr, nullptr, nullptr);
        }

        // fc2b + fused KF update
        {
            GSeg a = {a2, fc2bH, D_FC2_H, D_FC2_H};
            gemm_tc<<<dim3(NN * MM / 64, BB / 64), 128>>>(a, nil, nil, 1, fc2b_b, nullptr,
                nullptr, MM, 2, 0, nullptr, nullptr, dy, x_prior,
                out + (size_t)t * BB * MM);
        }
    }
}